// round 11
// baseline (speedup 1.0000x reference)
#include <cuda_runtime.h>
#include <cuda_fp16.h>
#include <math.h>

// Problem constants
#define BB 2
#define SS 2048
#define HID 2048
#define NH 16
#define NKVH 2
#define DH 256
#define ROT 64
#define MM (BB*SS)          // 4096 tokens
#define QGN (NH*DH*2)       // 8192
#define KVN (NKVH*DH)       // 512
#define ODIM (NH*DH)        // 4096

// Scratch (device globals)
__device__ __half g_hs  [(size_t)MM * HID];
__device__ __half g_wqt [(size_t)QGN * HID];
__device__ __half g_wkvt[(size_t)(2*KVN) * HID];
__device__ __half g_wot [(size_t)HID * ODIM];
__device__ float  g_qg  [(size_t)MM * QGN];
__device__ float  g_kv  [(size_t)MM * 2*KVN];
__device__ __half g_q   [(size_t)BB * NH  * SS * DH];
__device__ __half g_kr  [(size_t)BB * NKVH * SS * DH];
__device__ __half g_vr  [(size_t)BB * NKVH * DH * SS];   // [b][kvh][d][s]
__device__ __half g_attn[(size_t)MM * ODIM];

// ---------------- device helpers ----------------
__device__ __forceinline__ unsigned smem_u32(const void* p) {
    unsigned a;
    asm("{ .reg .u64 t; cvta.to.shared.u64 t, %1; cvt.u32.u64 %0, t; }" : "=r"(a) : "l"(p));
    return a;
}
__device__ __forceinline__ void mma_f16(float c[4], const unsigned a[4], const unsigned* b) {
    asm volatile(
        "mma.sync.aligned.m16n8k16.row.col.f32.f16.f16.f32 "
        "{%0,%1,%2,%3}, {%4,%5,%6,%7}, {%8,%9}, {%0,%1,%2,%3};\n"
        : "+f"(c[0]), "+f"(c[1]), "+f"(c[2]), "+f"(c[3])
        : "r"(a[0]), "r"(a[1]), "r"(a[2]), "r"(a[3]), "r"(b[0]), "r"(b[1]));
}
__device__ __forceinline__ void ldsm4(unsigned r[4], const __half* p) {
    unsigned a = smem_u32(p);
    asm volatile("ldmatrix.sync.aligned.m8n8.x4.shared.b16 {%0,%1,%2,%3}, [%4];\n"
                 : "=r"(r[0]), "=r"(r[1]), "=r"(r[2]), "=r"(r[3]) : "r"(a));
}
__device__ __forceinline__ void cp16(void* dst, const void* src) {
    unsigned d = (unsigned)__cvta_generic_to_shared(dst);
    asm volatile("cp.async.cg.shared.global [%0], [%1], 16;\n" :: "r"(d), "l"(src));
}
__device__ __forceinline__ void cp_commit() { asm volatile("cp.async.commit_group;\n"); }
__device__ __forceinline__ unsigned pack_h2(float a, float b) {
    __half2 h = __floats2half2_rn(a, b);
    return *(unsigned*)&h;
}

// ---------------------------------------------------------------------------
// Prep: fp32 -> fp16
// ---------------------------------------------------------------------------
__global__ __launch_bounds__(256) void half_kernel(const float* __restrict__ src,
                                                   __half* __restrict__ dst, int n8)
{
    for (int i = blockIdx.x * 256 + threadIdx.x; i < n8; i += gridDim.x * 256) {
        float4 v0 = ((const float4*)src)[i * 2];
        float4 v1 = ((const float4*)src)[i * 2 + 1];
        __half2 h[4];
        h[0] = __floats2half2_rn(v0.x, v0.y);
        h[1] = __floats2half2_rn(v0.z, v0.w);
        h[2] = __floats2half2_rn(v1.x, v1.y);
        h[3] = __floats2half2_rn(v1.z, v1.w);
        ((uint4*)dst)[i] = *(uint4*)h;
    }
}

// ---------------------------------------------------------------------------
// Prep: transpose + fp16. src [R][C] fp32 -> dst [C][R] fp16.
// ---------------------------------------------------------------------------
__global__ __launch_bounds__(256) void transpose_half_kernel(
    const float* __restrict__ src, __half* __restrict__ dst, int R, int C)
{
    __shared__ float t[32][33];
    const int x = blockIdx.x * 32 + threadIdx.x;
    const int y0 = blockIdx.y * 32;
#pragma unroll
    for (int i = 0; i < 32; i += 8)
        t[threadIdx.y + i][threadIdx.x] = src[(size_t)(y0 + threadIdx.y + i) * C + x];
    __syncthreads();
    const int nx = blockIdx.y * 32 + threadIdx.x;
    const int ny0 = blockIdx.x * 32;
#pragma unroll
    for (int i = 0; i < 32; i += 8)
        dst[(size_t)(ny0 + threadIdx.y + i) * R + nx] =
            __float2half(t[threadIdx.x][threadIdx.y + i]);
}

// ---------------------------------------------------------------------------
// fp16 GEMM (3-stage cp.async, BK=64), DUAL-OUTPUT: blocks bx < nbx1 compute
// C1 = A @ B1t (width N1), the rest compute C2 = A @ B2t (width N2).
// CTA tile 256x128, 8 warps (4x2), warp 64x64.
// ---------------------------------------------------------------------------
#define GS_STR 72   // halfs; 144B row stride (64 data + 8 pad)
#define TG_SMEM ((3*256*GS_STR + 3*128*GS_STR) * (int)sizeof(__half))

__global__ __launch_bounds__(256, 1) void hgemm_kernel(
    const __half* __restrict__ A,
    const __half* __restrict__ B1t, float* __restrict__ C1, int N1,
    const __half* __restrict__ B2t, float* __restrict__ C2, int N2,
    int K, int nbx1)
{
    extern __shared__ __half hsm[];
    __half* As = hsm;                        // [3][256][GS_STR]
    __half* Bs = hsm + 3 * 256 * GS_STR;     // [3][128][GS_STR]

    const int tid = threadIdx.x;
    int bx = blockIdx.x;
    const int by = blockIdx.y;
    const __half* Bt; float* C; int N;
    if (bx < nbx1) { Bt = B1t; C = C1; N = N1; }
    else           { bx -= nbx1; Bt = B2t; C = C2; N = N2; }

    const int lane = tid & 31;
    const int g = lane >> 2, t = lane & 3;
    const int wid = tid >> 5;
    const int m0 = (wid >> 1) * 64;
    const int n0 = (wid & 1) * 64;

    const int a_row = ((lane >> 3) & 1) * 8 + (lane & 7);
    const int a_kh  = (lane >> 4) * 8;
    const int b_row = ((lane >> 4) & 1) * 8 + (lane & 7);
    const int b_kh  = ((lane >> 3) & 1) * 8;

    const int nk = K >> 6;                   // BK=64

    auto issue = [&](int st, int k0) {
        __half* Ad = As + (size_t)st * 256 * GS_STR;
        __half* Bd = Bs + (size_t)st * 128 * GS_STR;
#pragma unroll
        for (int it = 0; it < 8; it++) {
            int idx = tid + it * 256;        // 0..2047
            int row = idx >> 3;              // 0..255
            int ch  = (idx & 7) * 8;         // 0..56
            cp16(Ad + row * GS_STR + ch, A + (size_t)(by * 256 + row) * K + k0 + ch);
        }
#pragma unroll
        for (int it = 0; it < 4; it++) {
            int idx = tid + it * 256;        // 0..1023
            int row = idx >> 3;              // 0..127
            int ch  = (idx & 7) * 8;
            cp16(Bd + row * GS_STR + ch, Bt + (size_t)(bx * 128 + row) * K + k0 + ch);
        }
        cp_commit();
    };

    issue(0, 0);
    if (nk > 1) issue(1, 64);
    if (nk > 2) issue(2, 128);

    float acc[4][8][4];
#pragma unroll
    for (int mt = 0; mt < 4; mt++)
#pragma unroll
        for (int nt = 0; nt < 8; nt++)
#pragma unroll
            for (int r = 0; r < 4; r++) acc[mt][nt][r] = 0.f;

    for (int i = 0; i < nk; i++) {
        const int st = i % 3;
        __half* Ad = As + (size_t)st * 256 * GS_STR;
        __half* Bd = Bs + (size_t)st * 128 * GS_STR;
        if (i + 2 < nk)      asm volatile("cp.async.wait_group 2;\n");
        else if (i + 1 < nk) asm volatile("cp.async.wait_group 1;\n");
        else                 asm volatile("cp.async.wait_group 0;\n");
        __syncthreads();

#pragma unroll
        for (int kk = 0; kk < 64; kk += 16) {
            unsigned a[4][4], bfr[4][4];
#pragma unroll
            for (int mt = 0; mt < 4; mt++)
                ldsm4(a[mt], Ad + (m0 + mt * 16 + a_row) * GS_STR + kk + a_kh);
#pragma unroll
            for (int p = 0; p < 4; p++)
                ldsm4(bfr[p], Bd + (n0 + p * 16 + b_row) * GS_STR + kk + b_kh);
#pragma unroll
            for (int mt = 0; mt < 4; mt++)
#pragma unroll
                for (int nt = 0; nt < 8; nt++)
                    mma_f16(acc[mt][nt], a[mt], &bfr[nt >> 1][(nt & 1) * 2]);
        }
        __syncthreads();
        if (i + 3 < nk) issue(st, (i + 3) * 64);
    }

#pragma unroll
    for (int mt = 0; mt < 4; mt++) {
        const int r = by * 256 + m0 + mt * 16 + g;
#pragma unroll
        for (int nt = 0; nt < 8; nt++) {
            const int c = bx * 128 + n0 + nt * 8 + 2 * t;
            *(float2*)(C + (size_t)r * N + c)       = make_float2(acc[mt][nt][0], acc[mt][nt][1]);
            *(float2*)(C + (size_t)(r + 8) * N + c) = make_float2(acc[mt][nt][2], acc[mt][nt][3]);
        }
    }
}

// ---------------------------------------------------------------------------
// Post-process v2: one WARP per (token, unit). Shfl-only reductions.
// ---------------------------------------------------------------------------
__global__ __launch_bounds__(256) void qkv_post_kernel(
    const float* __restrict__ cosp, const float* __restrict__ sinp,
    const float* __restrict__ qw, const float* __restrict__ kw)
{
    const int wi = blockIdx.x * 8 + (threadIdx.x >> 5);
    const int lane = threadIdx.x & 31;
    const int token = wi / 20;
    const int unit  = wi % 20;
    const int b = token >> 11;
    const int s = token & 2047;
    const int d0 = lane * 8;

    if (unit >= 18) {
        const int kvh = unit - 18;
        float4 v0 = *(const float4*)(g_kv + (size_t)token * (2*KVN) + 512 + kvh * 256 + d0);
        float4 v1 = *(const float4*)(g_kv + (size_t)token * (2*KVN) + 512 + kvh * 256 + d0 + 4);
        __half* dst = g_vr + (((size_t)b * NKVH + kvh) * DH + d0) * SS + s;
        dst[0 * SS] = __float2half(v0.x); dst[1 * SS] = __float2half(v0.y);
        dst[2 * SS] = __float2half(v0.z); dst[3 * SS] = __float2half(v0.w);
        dst[4 * SS] = __float2half(v1.x); dst[5 * SS] = __float2half(v1.y);
        dst[6 * SS] = __float2half(v1.z); dst[7 * SS] = __float2half(v1.w);
        return;
    }

    const float* src;
    const float* w;
    if (unit < 16) { src = g_qg + (size_t)token * QGN + unit * 512 + d0; w = qw + d0; }
    else           { src = g_kv + (size_t)token * (2*KVN) + (unit - 16) * 256 + d0; w = kw + d0; }

    float x[8];
    *(float4*)(x)     = *(const float4*)(src);
    *(float4*)(x + 4) = *(const float4*)(src + 4);

    float ss = 0.f;
#pragma unroll
    for (int j = 0; j < 8; j++) ss += x[j] * x[j];
#pragma unroll
    for (int o = 16; o; o >>= 1) ss += __shfl_xor_sync(0xffffffffu, ss, o);
    const float rsn = rsqrtf(ss * (1.0f / 256.0f) + 1e-6f);

    float xn[8];
#pragma unroll
    for (int j = 0; j < 8; j++) xn[j] = x[j] * rsn * (1.0f + w[j]);

    float rot[8];
#pragma unroll
    for (int j = 0; j < 8; j++) rot[j] = __shfl_xor_sync(0xffffffffu, xn[j], 4);
    if (lane < 8) {
        float cs[8], sn[8];
        *(float4*)(cs)     = *(const float4*)(cosp + (size_t)token * ROT + d0);
        *(float4*)(cs + 4) = *(const float4*)(cosp + (size_t)token * ROT + d0 + 4);
        *(float4*)(sn)     = *(const float4*)(sinp + (size_t)token * ROT + d0);
        *(float4*)(sn + 4) = *(const float4*)(sinp + (size_t)token * ROT + d0 + 4);
#pragma unroll
        for (int j = 0; j < 8; j++) {
            float rr = (lane & 4) ? rot[j] : -rot[j];
            xn[j] = xn[j] * cs[j] + rr * sn[j];
        }
    }

    __half2 h[4];
    if (unit < 16) {
#pragma unroll
        for (int j = 0; j < 4; j++)
            h[j] = __floats2half2_rn(xn[2*j] * 0.0625f, xn[2*j+1] * 0.0625f);
        *(uint4*)(g_q + (((size_t)b * NH + unit) * SS + s) * DH + d0) = *(uint4*)h;
    } else {
#pragma unroll
        for (int j = 0; j < 4; j++)
            h[j] = __floats2half2_rn(xn[2*j], xn[2*j+1]);
        *(uint4*)(g_kr + (((size_t)b * NKVH + (unit - 16)) * SS + s) * DH + d0) = *(uint4*)h;
    }
}

// ---------------------------------------------------------------------------
// Flash attention v7: warp-autonomous 16-row warps, register-resident P.
// grid (bh=32, qtiles=16): heavy q-tiles ALL start in wave 1.
// Fully-masked warp tiles skipped.
// ---------------------------------------------------------------------------
#define QS_STR 264
#define KS_STR 264
#define VS_STR 72
#define FL_SMEM ((128*QS_STR + 2*64*KS_STR + 256*VS_STR) * 2)

__global__ __launch_bounds__(256, 1) void flash_kernel()
{
    extern __shared__ __half smh[];
    __half* Qs = smh;                        // [128][QS_STR]
    __half* Ks = Qs + 128 * QS_STR;          // [2][64][KS_STR]
    __half* Vs = Ks + 2 * 64 * KS_STR;       // [256][VS_STR] ([d][key])

    const int tid = threadIdx.x;
    const int lane = tid & 31;
    const int g = lane >> 2, t = lane & 3;
    const int w = tid >> 5;
    const int rb = w * 16;

    const int a_row = ((lane >> 3) & 1) * 8 + (lane & 7);
    const int a_kh  = (lane >> 4) * 8;
    const int b_row = ((lane >> 4) & 1) * 8 + (lane & 7);
    const int b_kh  = ((lane >> 3) & 1) * 8;

    const int qt = (int)gridDim.y - 1 - (int)blockIdx.y;   // heavy first
    const int b  = blockIdx.x >> 4;
    const int h  = blockIdx.x & 15;
    const int kvh = h >> 3;
    const int q0 = qt * 128;

    const __half* Qp  = g_q  + (((size_t)b * NH + h) * SS + q0) * DH;
    const __half* Kp  = g_kr + ((size_t)b * NKVH + kvh) * SS * DH;
    const __half* VpT = g_vr + ((size_t)b * NKVH + kvh) * DH * SS;

    auto issueK = [&](int kt, int st) {
        const __half* Kt = Kp + (size_t)(kt * 64) * DH;
        __half* Kd = Ks + st * 64 * KS_STR;
#pragma unroll
        for (int it = 0; it < 8; it++) {
            const int idx = tid + it * 256;
            const int key = idx >> 5;
            const int col = (idx & 31) * 8;
            cp16(Kd + key * KS_STR + col, Kt + (size_t)key * DH + col);
        }
    };
    auto issueV = [&](int kt) {
#pragma unroll
        for (int it = 0; it < 8; it++) {
            const int idx = tid + it * 256;
            const int dl = idx >> 3;
            const int kc = (idx & 7) * 8;
            cp16(Vs + dl * VS_STR + kc, VpT + (size_t)dl * SS + kt * 64 + kc);
        }
    };

    // Q resident
#pragma unroll
    for (int it = 0; it < 16; it++) {
        const int idx = tid + it * 256;
        const int r = idx >> 5;
        const int c = (idx & 31) * 8;
        *(uint4*)&Qs[r * QS_STR + c] = *(const uint4*)(Qp + (size_t)r * DH + c);
    }

    float o[32][4];
    float m[2], l[2];
#pragma unroll
    for (int cc = 0; cc < 32; cc++)
#pragma unroll
        for (int r = 0; r < 4; r++) o[cc][r] = 0.f;
    m[0] = m[1] = -1e30f; l[0] = l[1] = 0.f;

    const int ktmax = 2 * qt + 1;

    issueK(0, 0);
    cp_commit();

    for (int kt = 0; kt <= ktmax; kt++) {
        __syncthreads();
        if (kt + 1 <= ktmax) issueK(kt + 1, (kt + 1) & 1);
        issueV(kt);
        cp_commit();

        asm volatile("cp.async.wait_group 1;\n");
        __syncthreads();

        // fully-masked warp tile? (all cols > all rows)
        const bool active = (kt * 64 <= q0 + rb + 15);

        float s[8][4];
        if (active) {
            const __half* Kd = Ks + (kt & 1) * 64 * KS_STR;
#pragma unroll
            for (int nt = 0; nt < 8; nt++)
#pragma unroll
                for (int r = 0; r < 4; r++) s[nt][r] = 0.f;

#pragma unroll
            for (int kk = 0; kk < 256; kk += 16) {
                unsigned a[4], bq[4][4];
                ldsm4(a, Qs + (rb + a_row) * QS_STR + kk + a_kh);
#pragma unroll
                for (int p = 0; p < 4; p++)
                    ldsm4(bq[p], Kd + (p * 16 + b_row) * KS_STR + kk + b_kh);
#pragma unroll
                for (int nt = 0; nt < 8; nt++)
                    mma_f16(s[nt], a, &bq[nt >> 1][(nt & 1) * 2]);
            }

            if (kt >= 2 * qt) {
#pragma unroll
                for (int nt = 0; nt < 8; nt++)
#pragma unroll
                    for (int r = 0; r < 4; r++) {
                        const int row = q0 + rb + (r >> 1) * 8 + g;
                        const int col = kt * 64 + nt * 8 + 2 * t + (r & 1);
                        if (col > row) s[nt][r] = -1e30f;
                    }
            }

            float al[2];
#pragma unroll
            for (int hh = 0; hh < 2; hh++) {
                float v = -1e30f;
#pragma unroll
                for (int nt = 0; nt < 8; nt++)
                    v = fmaxf(v, fmaxf(s[nt][hh * 2], s[nt][hh * 2 + 1]));
                v = fmaxf(v, __shfl_xor_sync(0xffffffffu, v, 1));
                v = fmaxf(v, __shfl_xor_sync(0xffffffffu, v, 2));
                float mn = fmaxf(m[hh], v);
                al[hh] = __expf(m[hh] - mn);
                m[hh] = mn;
                float rs = 0.f;
#pragma unroll
                for (int nt = 0; nt < 8; nt++) {
                    float p0 = __expf(s[nt][hh * 2]     - mn);
                    float p1 = __expf(s[nt][hh * 2 + 1] - mn);
                    s[nt][hh * 2] = p0; s[nt][hh * 2 + 1] = p1;
                    rs += p0 + p1;
                }
                rs += __shfl_xor_sync(0xffffffffu, rs, 1);
                rs += __shfl_xor_sync(0xffffffffu, rs, 2);
                l[hh] = l[hh] * al[hh] + rs;
#pragma unroll
                for (int cc = 0; cc < 32; cc++) {
                    o[cc][hh * 2]     *= al[hh];
                    o[cc][hh * 2 + 1] *= al[hh];
                }
            }
        }

        asm volatile("cp.async.wait_group 0;\n");
        __syncthreads();

        if (active) {
#pragma unroll
            for (int kk4 = 0; kk4 < 4; kk4++) {
                unsigned pa[4];
                pa[0] = pack_h2(s[2*kk4][0],   s[2*kk4][1]);
                pa[1] = pack_h2(s[2*kk4][2],   s[2*kk4][3]);
                pa[2] = pack_h2(s[2*kk4+1][0], s[2*kk4+1][1]);
                pa[3] = pack_h2(s[2*kk4+1][2], s[2*kk4+1][3]);
#pragma unroll
                for (int half = 0; half < 2; half++) {
                    unsigned bv[8][4];
#pragma unroll
                    for (int p = 0; p < 8; p++)
                        ldsm4(bv[p], Vs + (half * 128 + p * 16 + b_row) * VS_STR + kk4 * 16 + b_kh);
#pragma unroll
                    for (int nt = 0; nt < 16; nt++)
                        mma_f16(o[half * 16 + nt], pa, &bv[nt >> 1][(nt & 1) * 2]);
                }
            }
        }
    }

    // ---- epilogue: /l, * sigmoid(gate) ----
#pragma unroll
    for (int hh = 0; hh < 2; hh++) {
        const int row = q0 + rb + hh * 8 + g;
        const size_t token = (size_t)b * SS + row;
        const float inv = 1.f / l[hh];
#pragma unroll
        for (int cc = 0; cc < 32; cc++) {
            const int col = cc * 8 + 2 * t;
            float2 gt = *(const float2*)(g_qg + token * QGN + h * 512 + 256 + col);
            float ox = o[cc][hh * 2]     * inv / (1.f + __expf(-gt.x));
            float oy = o[cc][hh * 2 + 1] * inv / (1.f + __expf(-gt.y));
            *(__half2*)(g_attn + token * ODIM + h * 256 + col) =
                __floats2half2_rn(ox, oy);
        }
    }
}

// ---------------------------------------------------------------------------
extern "C" void kernel_launch(void* const* d_in, const int* in_sizes, int n_in,
                              void* d_out, int out_size)
{
    (void)in_sizes; (void)n_in; (void)out_size;
    const float* hs   = (const float*)d_in[0];
    const float* cosp = (const float*)d_in[1];
    const float* sinp = (const float*)d_in[2];
    const float* Wq   = (const float*)d_in[3];
    const float* Wk   = (const float*)d_in[4];
    const float* Wv   = (const float*)d_in[5];
    const float* Wo   = (const float*)d_in[6];
    const float* qw   = (const float*)d_in[7];
    const float* kw   = (const float*)d_in[8];
    float* out = (float*)d_out;

    __half *p_hs, *p_wqt, *p_wkvt, *p_wot, *p_attn;
    float *p_qg, *p_kv;
    cudaGetSymbolAddress((void**)&p_hs,   g_hs);
    cudaGetSymbolAddress((void**)&p_wqt,  g_wqt);
    cudaGetSymbolAddress((void**)&p_wkvt, g_wkvt);
    cudaGetSymbolAddress((void**)&p_wot,  g_wot);
    cudaGetSymbolAddress((void**)&p_qg,   g_qg);
    cudaGetSymbolAddress((void**)&p_kv,   g_kv);
    cudaGetSymbolAddress((void**)&p_attn, g_attn);

    // 0) Prep
    half_kernel<<<1024, 256>>>(hs, p_hs, MM * HID / 8);
    transpose_half_kernel<<<dim3(QGN / 32, HID / 32), dim3(32, 8)>>>(Wq, p_wqt, HID, QGN);
    transpose_half_kernel<<<dim3(KVN / 32, HID / 32), dim3(32, 8)>>>(Wk, p_wkvt, HID, KVN);
    transpose_half_kernel<<<dim3(KVN / 32, HID / 32), dim3(32, 8)>>>(Wv, p_wkvt + (size_t)KVN * HID, HID, KVN);
    transpose_half_kernel<<<dim3(HID / 32, ODIM / 32), dim3(32, 8)>>>(Wo, p_wot, ODIM, HID);

    // 1) Fused QG + KV projection
    cudaFuncSetAttribute(hgemm_kernel, cudaFuncAttributeMaxDynamicSharedMemorySize, TG_SMEM);
    hgemm_kernel<<<dim3(QGN / 128 + 2*KVN / 128, MM / 256), 256, TG_SMEM>>>(
        p_hs, p_wqt, p_qg, QGN, p_wkvt, p_kv, 2*KVN, HID, QGN / 128);

    // 2) RMSNorm + RoPE + V transpose
    qkv_post_kernel<<<MM * 20 / 8, 256>>>(cosp, sinp, qw, kw);

    // 3) Flash attention + gate (heavy q-tiles in wave 1)
    cudaFuncSetAttribute(flash_kernel, cudaFuncAttributeMaxDynamicSharedMemorySize, FL_SMEM);
    flash_kernel<<<dim3(BB * NH, SS / 128), 256, FL_SMEM>>>();

    // 4) Output projection
    hgemm_kernel<<<dim3(HID / 128, MM / 256), 256, TG_SMEM>>>(
        p_attn, p_wot, out, HID, p_wot, out, HID, ODIM, HID / 128);
}

// round 12
// speedup vs baseline: 1.3651x; 1.3651x over previous
#include <cuda_runtime.h>
#include <cuda_fp16.h>
#include <math.h>

// Problem constants
#define BB 2
#define SS 2048
#define HID 2048
#define NH 16
#define NKVH 2
#define DH 256
#define ROT 64
#define MM (BB*SS)          // 4096 tokens
#define QGN (NH*DH*2)       // 8192
#define KVN (NKVH*DH)       // 512
#define ODIM (NH*DH)        // 4096

// Scratch (device globals)
__device__ __half g_hs  [(size_t)MM * HID];
__device__ __half g_wqt [(size_t)QGN * HID];
__device__ __half g_wkvt[(size_t)(2*KVN) * HID];
__device__ __half g_wot [(size_t)HID * ODIM];
__device__ float  g_qg  [(size_t)MM * QGN];
__device__ float  g_kv  [(size_t)MM * 2*KVN];
__device__ __half g_q   [(size_t)BB * NH  * SS * DH];
__device__ __half g_kr  [(size_t)BB * NKVH * SS * DH];
__device__ __half g_vr  [(size_t)BB * NKVH * DH * SS];   // [b][kvh][d][s]
__device__ __half g_attn[(size_t)MM * ODIM];

// ---------------- device helpers ----------------
__device__ __forceinline__ unsigned smem_u32(const void* p) {
    unsigned a;
    asm("{ .reg .u64 t; cvta.to.shared.u64 t, %1; cvt.u32.u64 %0, t; }" : "=r"(a) : "l"(p));
    return a;
}
__device__ __forceinline__ void mma_f16(float c[4], const unsigned a[4], const unsigned* b) {
    asm volatile(
        "mma.sync.aligned.m16n8k16.row.col.f32.f16.f16.f32 "
        "{%0,%1,%2,%3}, {%4,%5,%6,%7}, {%8,%9}, {%0,%1,%2,%3};\n"
        : "+f"(c[0]), "+f"(c[1]), "+f"(c[2]), "+f"(c[3])
        : "r"(a[0]), "r"(a[1]), "r"(a[2]), "r"(a[3]), "r"(b[0]), "r"(b[1]));
}
__device__ __forceinline__ void ldsm4(unsigned r[4], const __half* p) {
    unsigned a = smem_u32(p);
    asm volatile("ldmatrix.sync.aligned.m8n8.x4.shared.b16 {%0,%1,%2,%3}, [%4];\n"
                 : "=r"(r[0]), "=r"(r[1]), "=r"(r[2]), "=r"(r[3]) : "r"(a));
}
__device__ __forceinline__ void cp16(void* dst, const void* src) {
    unsigned d = (unsigned)__cvta_generic_to_shared(dst);
    asm volatile("cp.async.cg.shared.global [%0], [%1], 16;\n" :: "r"(d), "l"(src));
}
__device__ __forceinline__ void cp_commit() { asm volatile("cp.async.commit_group;\n"); }
__device__ __forceinline__ unsigned pack_h2(float a, float b) {
    __half2 h = __floats2half2_rn(a, b);
    return *(unsigned*)&h;
}

// ---------------------------------------------------------------------------
// Prep: fp32 -> fp16
// ---------------------------------------------------------------------------
__global__ __launch_bounds__(256) void half_kernel(const float* __restrict__ src,
                                                   __half* __restrict__ dst, int n8)
{
    for (int i = blockIdx.x * 256 + threadIdx.x; i < n8; i += gridDim.x * 256) {
        float4 v0 = ((const float4*)src)[i * 2];
        float4 v1 = ((const float4*)src)[i * 2 + 1];
        __half2 h[4];
        h[0] = __floats2half2_rn(v0.x, v0.y);
        h[1] = __floats2half2_rn(v0.z, v0.w);
        h[2] = __floats2half2_rn(v1.x, v1.y);
        h[3] = __floats2half2_rn(v1.z, v1.w);
        ((uint4*)dst)[i] = *(uint4*)h;
    }
}

// ---------------------------------------------------------------------------
// Prep: transpose + fp16. src [R][C] fp32 -> dst [C][R] fp16.
// ---------------------------------------------------------------------------
__global__ __launch_bounds__(256) void transpose_half_kernel(
    const float* __restrict__ src, __half* __restrict__ dst, int R, int C)
{
    __shared__ float t[32][33];
    const int x = blockIdx.x * 32 + threadIdx.x;
    const int y0 = blockIdx.y * 32;
#pragma unroll
    for (int i = 0; i < 32; i += 8)
        t[threadIdx.y + i][threadIdx.x] = src[(size_t)(y0 + threadIdx.y + i) * C + x];
    __syncthreads();
    const int nx = blockIdx.y * 32 + threadIdx.x;
    const int ny0 = blockIdx.x * 32;
#pragma unroll
    for (int i = 0; i < 32; i += 8)
        dst[(size_t)(ny0 + threadIdx.y + i) * R + nx] =
            __float2half(t[threadIdx.x][threadIdx.y + i]);
}

// ---------------------------------------------------------------------------
// fp16 GEMM (3-stage cp.async, BK=32), DUAL-OUTPUT — round-10 version.
// CTA tile 256x128, 8 warps (4x2), warp 64x64.
// ---------------------------------------------------------------------------
#define GS_STR 40
#define TG_SMEM ((3*256*GS_STR + 3*128*GS_STR) * (int)sizeof(__half))

__global__ __launch_bounds__(256, 1) void hgemm_kernel(
    const __half* __restrict__ A,
    const __half* __restrict__ B1t, float* __restrict__ C1, int N1,
    const __half* __restrict__ B2t, float* __restrict__ C2, int N2,
    int K, int nbx1)
{
    extern __shared__ __half hsm[];
    __half* As = hsm;
    __half* Bs = hsm + 3 * 256 * GS_STR;

    const int tid = threadIdx.x;
    int bx = blockIdx.x;
    const int by = blockIdx.y;
    const __half* Bt; float* C; int N;
    if (bx < nbx1) { Bt = B1t; C = C1; N = N1; }
    else           { bx -= nbx1; Bt = B2t; C = C2; N = N2; }

    const int lane = tid & 31;
    const int g = lane >> 2, t = lane & 3;
    const int wid = tid >> 5;
    const int m0 = (wid >> 1) * 64;
    const int n0 = (wid & 1) * 64;

    const int a_row = ((lane >> 3) & 1) * 8 + (lane & 7);
    const int a_kh  = (lane >> 4) * 8;
    const int b_row = ((lane >> 4) & 1) * 8 + (lane & 7);
    const int b_kh  = ((lane >> 3) & 1) * 8;

    const int nk = K >> 5;

    auto issue = [&](int st, int k0) {
        __half* Ad = As + (size_t)st * 256 * GS_STR;
        __half* Bd = Bs + (size_t)st * 128 * GS_STR;
#pragma unroll
        for (int it = 0; it < 4; it++) {
            int idx = tid + it * 256;
            int row = idx >> 2;
            int ch  = (idx & 3) * 8;
            cp16(Ad + row * GS_STR + ch, A + (size_t)(by * 256 + row) * K + k0 + ch);
        }
#pragma unroll
        for (int it = 0; it < 2; it++) {
            int idx = tid + it * 256;
            int row = idx >> 2;
            int ch  = (idx & 3) * 8;
            cp16(Bd + row * GS_STR + ch, Bt + (size_t)(bx * 128 + row) * K + k0 + ch);
        }
        cp_commit();
    };

    issue(0, 0);
    if (nk > 1) issue(1, 32);
    if (nk > 2) issue(2, 64);

    float acc[4][8][4];
#pragma unroll
    for (int mt = 0; mt < 4; mt++)
#pragma unroll
        for (int nt = 0; nt < 8; nt++)
#pragma unroll
            for (int r = 0; r < 4; r++) acc[mt][nt][r] = 0.f;

    for (int i = 0; i < nk; i++) {
        const int st = i % 3;
        __half* Ad = As + (size_t)st * 256 * GS_STR;
        __half* Bd = Bs + (size_t)st * 128 * GS_STR;
        if (i + 2 < nk)      asm volatile("cp.async.wait_group 2;\n");
        else if (i + 1 < nk) asm volatile("cp.async.wait_group 1;\n");
        else                 asm volatile("cp.async.wait_group 0;\n");
        __syncthreads();

#pragma unroll
        for (int kk = 0; kk < 32; kk += 16) {
            unsigned a[4][4], bfr[4][4];
#pragma unroll
            for (int mt = 0; mt < 4; mt++)
                ldsm4(a[mt], Ad + (m0 + mt * 16 + a_row) * GS_STR + kk + a_kh);
#pragma unroll
            for (int p = 0; p < 4; p++)
                ldsm4(bfr[p], Bd + (n0 + p * 16 + b_row) * GS_STR + kk + b_kh);
#pragma unroll
            for (int mt = 0; mt < 4; mt++)
#pragma unroll
                for (int nt = 0; nt < 8; nt++)
                    mma_f16(acc[mt][nt], a[mt], &bfr[nt >> 1][(nt & 1) * 2]);
        }
        __syncthreads();
        if (i + 3 < nk) issue(st, (i + 3) * 32);
    }

#pragma unroll
    for (int mt = 0; mt < 4; mt++) {
        const int r = by * 256 + m0 + mt * 16 + g;
#pragma unroll
        for (int nt = 0; nt < 8; nt++) {
            const int c = bx * 128 + n0 + nt * 8 + 2 * t;
            *(float2*)(C + (size_t)r * N + c)       = make_float2(acc[mt][nt][0], acc[mt][nt][1]);
            *(float2*)(C + (size_t)(r + 8) * N + c) = make_float2(acc[mt][nt][2], acc[mt][nt][3]);
        }
    }
}

// ---------------------------------------------------------------------------
// Post-process v2: one WARP per (token, unit). Shfl-only reductions.
// ---------------------------------------------------------------------------
__global__ __launch_bounds__(256) void qkv_post_kernel(
    const float* __restrict__ cosp, const float* __restrict__ sinp,
    const float* __restrict__ qw, const float* __restrict__ kw)
{
    const int wi = blockIdx.x * 8 + (threadIdx.x >> 5);
    const int lane = threadIdx.x & 31;
    const int token = wi / 20;
    const int unit  = wi % 20;
    const int b = token >> 11;
    const int s = token & 2047;
    const int d0 = lane * 8;

    if (unit >= 18) {
        const int kvh = unit - 18;
        float4 v0 = *(const float4*)(g_kv + (size_t)token * (2*KVN) + 512 + kvh * 256 + d0);
        float4 v1 = *(const float4*)(g_kv + (size_t)token * (2*KVN) + 512 + kvh * 256 + d0 + 4);
        __half* dst = g_vr + (((size_t)b * NKVH + kvh) * DH + d0) * SS + s;
        dst[0 * SS] = __float2half(v0.x); dst[1 * SS] = __float2half(v0.y);
        dst[2 * SS] = __float2half(v0.z); dst[3 * SS] = __float2half(v0.w);
        dst[4 * SS] = __float2half(v1.x); dst[5 * SS] = __float2half(v1.y);
        dst[6 * SS] = __float2half(v1.z); dst[7 * SS] = __float2half(v1.w);
        return;
    }

    const float* src;
    const float* w;
    if (unit < 16) { src = g_qg + (size_t)token * QGN + unit * 512 + d0; w = qw + d0; }
    else           { src = g_kv + (size_t)token * (2*KVN) + (unit - 16) * 256 + d0; w = kw + d0; }

    float x[8];
    *(float4*)(x)     = *(const float4*)(src);
    *(float4*)(x + 4) = *(const float4*)(src + 4);

    float ss = 0.f;
#pragma unroll
    for (int j = 0; j < 8; j++) ss += x[j] * x[j];
#pragma unroll
    for (int o = 16; o; o >>= 1) ss += __shfl_xor_sync(0xffffffffu, ss, o);
    const float rsn = rsqrtf(ss * (1.0f / 256.0f) + 1e-6f);

    float xn[8];
#pragma unroll
    for (int j = 0; j < 8; j++) xn[j] = x[j] * rsn * (1.0f + w[j]);

    float rot[8];
#pragma unroll
    for (int j = 0; j < 8; j++) rot[j] = __shfl_xor_sync(0xffffffffu, xn[j], 4);
    if (lane < 8) {
        float cs[8], sn[8];
        *(float4*)(cs)     = *(const float4*)(cosp + (size_t)token * ROT + d0);
        *(float4*)(cs + 4) = *(const float4*)(cosp + (size_t)token * ROT + d0 + 4);
        *(float4*)(sn)     = *(const float4*)(sinp + (size_t)token * ROT + d0);
        *(float4*)(sn + 4) = *(const float4*)(sinp + (size_t)token * ROT + d0 + 4);
#pragma unroll
        for (int j = 0; j < 8; j++) {
            float rr = (lane & 4) ? rot[j] : -rot[j];
            xn[j] = xn[j] * cs[j] + rr * sn[j];
        }
    }

    __half2 h[4];
    if (unit < 16) {
#pragma unroll
        for (int j = 0; j < 4; j++)
            h[j] = __floats2half2_rn(xn[2*j] * 0.0625f, xn[2*j+1] * 0.0625f);
        *(uint4*)(g_q + (((size_t)b * NH + unit) * SS + s) * DH + d0) = *(uint4*)h;
    } else {
#pragma unroll
        for (int j = 0; j < 4; j++)
            h[j] = __floats2half2_rn(xn[2*j], xn[2*j+1]);
        *(uint4*)(g_kr + (((size_t)b * NKVH + (unit - 16)) * SS + s) * DH + d0) = *(uint4*)h;
    }
}

// ---------------------------------------------------------------------------
// Flash attention v7: warp-autonomous 16-row warps, register-resident P.
// grid (bh=32, qtiles=16): heavy q-tiles ALL start in wave 1.
// Fully-masked warp tiles skipped.
// ---------------------------------------------------------------------------
#define QS_STR 264
#define KS_STR 264
#define VS_STR 72
#define FL_SMEM ((128*QS_STR + 2*64*KS_STR + 256*VS_STR) * 2)

__global__ __launch_bounds__(256, 1) void flash_kernel()
{
    extern __shared__ __half smh[];
    __half* Qs = smh;                        // [128][QS_STR]
    __half* Ks = Qs + 128 * QS_STR;          // [2][64][KS_STR]
    __half* Vs = Ks + 2 * 64 * KS_STR;       // [256][VS_STR] ([d][key])

    const int tid = threadIdx.x;
    const int lane = tid & 31;
    const int g = lane >> 2, t = lane & 3;
    const int w = tid >> 5;
    const int rb = w * 16;

    const int a_row = ((lane >> 3) & 1) * 8 + (lane & 7);
    const int a_kh  = (lane >> 4) * 8;
    const int b_row = ((lane >> 4) & 1) * 8 + (lane & 7);
    const int b_kh  = ((lane >> 3) & 1) * 8;

    const int qt = (int)gridDim.y - 1 - (int)blockIdx.y;   // heavy first
    const int b  = blockIdx.x >> 4;
    const int h  = blockIdx.x & 15;
    const int kvh = h >> 3;
    const int q0 = qt * 128;

    const __half* Qp  = g_q  + (((size_t)b * NH + h) * SS + q0) * DH;
    const __half* Kp  = g_kr + ((size_t)b * NKVH + kvh) * SS * DH;
    const __half* VpT = g_vr + ((size_t)b * NKVH + kvh) * DH * SS;

    auto issueK = [&](int kt, int st) {
        const __half* Kt = Kp + (size_t)(kt * 64) * DH;
        __half* Kd = Ks + st * 64 * KS_STR;
#pragma unroll
        for (int it = 0; it < 8; it++) {
            const int idx = tid + it * 256;
            const int key = idx >> 5;
            const int col = (idx & 31) * 8;
            cp16(Kd + key * KS_STR + col, Kt + (size_t)key * DH + col);
        }
    };
    auto issueV = [&](int kt) {
#pragma unroll
        for (int it = 0; it < 8; it++) {
            const int idx = tid + it * 256;
            const int dl = idx >> 3;
            const int kc = (idx & 7) * 8;
            cp16(Vs + dl * VS_STR + kc, VpT + (size_t)dl * SS + kt * 64 + kc);
        }
    };

    // Q resident
#pragma unroll
    for (int it = 0; it < 16; it++) {
        const int idx = tid + it * 256;
        const int r = idx >> 5;
        const int c = (idx & 31) * 8;
        *(uint4*)&Qs[r * QS_STR + c] = *(const uint4*)(Qp + (size_t)r * DH + c);
    }

    float o[32][4];
    float m[2], l[2];
#pragma unroll
    for (int cc = 0; cc < 32; cc++)
#pragma unroll
        for (int r = 0; r < 4; r++) o[cc][r] = 0.f;
    m[0] = m[1] = -1e30f; l[0] = l[1] = 0.f;

    const int ktmax = 2 * qt + 1;

    issueK(0, 0);
    cp_commit();

    for (int kt = 0; kt <= ktmax; kt++) {
        __syncthreads();
        if (kt + 1 <= ktmax) issueK(kt + 1, (kt + 1) & 1);
        issueV(kt);
        cp_commit();

        asm volatile("cp.async.wait_group 1;\n");
        __syncthreads();

        // fully-masked warp tile? (all cols > all rows)
        const bool active = (kt * 64 <= q0 + rb + 15);

        float s[8][4];
        if (active) {
            const __half* Kd = Ks + (kt & 1) * 64 * KS_STR;
#pragma unroll
            for (int nt = 0; nt < 8; nt++)
#pragma unroll
                for (int r = 0; r < 4; r++) s[nt][r] = 0.f;

#pragma unroll
            for (int kk = 0; kk < 256; kk += 16) {
                unsigned a[4], bq[4][4];
                ldsm4(a, Qs + (rb + a_row) * QS_STR + kk + a_kh);
#pragma unroll
                for (int p = 0; p < 4; p++)
                    ldsm4(bq[p], Kd + (p * 16 + b_row) * KS_STR + kk + b_kh);
#pragma unroll
                for (int nt = 0; nt < 8; nt++)
                    mma_f16(s[nt], a, &bq[nt >> 1][(nt & 1) * 2]);
            }

            if (kt >= 2 * qt) {
#pragma unroll
                for (int nt = 0; nt < 8; nt++)
#pragma unroll
                    for (int r = 0; r < 4; r++) {
                        const int row = q0 + rb + (r >> 1) * 8 + g;
                        const int col = kt * 64 + nt * 8 + 2 * t + (r & 1);
                        if (col > row) s[nt][r] = -1e30f;
                    }
            }

            float al[2];
#pragma unroll
            for (int hh = 0; hh < 2; hh++) {
                float v = -1e30f;
#pragma unroll
                for (int nt = 0; nt < 8; nt++)
                    v = fmaxf(v, fmaxf(s[nt][hh * 2], s[nt][hh * 2 + 1]));
                v = fmaxf(v, __shfl_xor_sync(0xffffffffu, v, 1));
                v = fmaxf(v, __shfl_xor_sync(0xffffffffu, v, 2));
                float mn = fmaxf(m[hh], v);
                al[hh] = __expf(m[hh] - mn);
                m[hh] = mn;
                float rs = 0.f;
#pragma unroll
                for (int nt = 0; nt < 8; nt++) {
                    float p0 = __expf(s[nt][hh * 2]     - mn);
                    float p1 = __expf(s[nt][hh * 2 + 1] - mn);
                    s[nt][hh * 2] = p0; s[nt][hh * 2 + 1] = p1;
                    rs += p0 + p1;
                }
                rs += __shfl_xor_sync(0xffffffffu, rs, 1);
                rs += __shfl_xor_sync(0xffffffffu, rs, 2);
                l[hh] = l[hh] * al[hh] + rs;
#pragma unroll
                for (int cc = 0; cc < 32; cc++) {
                    o[cc][hh * 2]     *= al[hh];
                    o[cc][hh * 2 + 1] *= al[hh];
                }
            }
        }

        asm volatile("cp.async.wait_group 0;\n");
        __syncthreads();

        if (active) {
#pragma unroll
            for (int kk4 = 0; kk4 < 4; kk4++) {
                unsigned pa[4];
                pa[0] = pack_h2(s[2*kk4][0],   s[2*kk4][1]);
                pa[1] = pack_h2(s[2*kk4][2],   s[2*kk4][3]);
                pa[2] = pack_h2(s[2*kk4+1][0], s[2*kk4+1][1]);
                pa[3] = pack_h2(s[2*kk4+1][2], s[2*kk4+1][3]);
#pragma unroll
                for (int half = 0; half < 2; half++) {
                    unsigned bv[8][4];
#pragma unroll
                    for (int p = 0; p < 8; p++)
                        ldsm4(bv[p], Vs + (half * 128 + p * 16 + b_row) * VS_STR + kk4 * 16 + b_kh);
#pragma unroll
                    for (int nt = 0; nt < 16; nt++)
                        mma_f16(o[half * 16 + nt], pa, &bv[nt >> 1][(nt & 1) * 2]);
                }
            }
        }
    }

    // ---- epilogue: /l, * sigmoid(gate) ----
#pragma unroll
    for (int hh = 0; hh < 2; hh++) {
        const int row = q0 + rb + hh * 8 + g;
        const size_t token = (size_t)b * SS + row;
        const float inv = 1.f / l[hh];
#pragma unroll
        for (int cc = 0; cc < 32; cc++) {
            const int col = cc * 8 + 2 * t;
            float2 gt = *(const float2*)(g_qg + token * QGN + h * 512 + 256 + col);
            float ox = o[cc][hh * 2]     * inv / (1.f + __expf(-gt.x));
            float oy = o[cc][hh * 2 + 1] * inv / (1.f + __expf(-gt.y));
            *(__half2*)(g_attn + token * ODIM + h * 256 + col) =
                __floats2half2_rn(ox, oy);
        }
    }
}

// ---------------------------------------------------------------------------
extern "C" void kernel_launch(void* const* d_in, const int* in_sizes, int n_in,
                              void* d_out, int out_size)
{
    (void)in_sizes; (void)n_in; (void)out_size;
    const float* hs   = (const float*)d_in[0];
    const float* cosp = (const float*)d_in[1];
    const float* sinp = (const float*)d_in[2];
    const float* Wq   = (const float*)d_in[3];
    const float* Wk   = (const float*)d_in[4];
    const float* Wv   = (const float*)d_in[5];
    const float* Wo   = (const float*)d_in[6];
    const float* qw   = (const float*)d_in[7];
    const float* kw   = (const float*)d_in[8];
    float* out = (float*)d_out;

    __half *p_hs, *p_wqt, *p_wkvt, *p_wot, *p_attn;
    float *p_qg, *p_kv;
    cudaGetSymbolAddress((void**)&p_hs,   g_hs);
    cudaGetSymbolAddress((void**)&p_wqt,  g_wqt);
    cudaGetSymbolAddress((void**)&p_wkvt, g_wkvt);
    cudaGetSymbolAddress((void**)&p_wot,  g_wot);
    cudaGetSymbolAddress((void**)&p_qg,   g_qg);
    cudaGetSymbolAddress((void**)&p_kv,   g_kv);
    cudaGetSymbolAddress((void**)&p_attn, g_attn);

    // 0) Prep
    half_kernel<<<1024, 256>>>(hs, p_hs, MM * HID / 8);
    transpose_half_kernel<<<dim3(QGN / 32, HID / 32), dim3(32, 8)>>>(Wq, p_wqt, HID, QGN);
    transpose_half_kernel<<<dim3(KVN / 32, HID / 32), dim3(32, 8)>>>(Wk, p_wkvt, HID, KVN);
    transpose_half_kernel<<<dim3(KVN / 32, HID / 32), dim3(32, 8)>>>(Wv, p_wkvt + (size_t)KVN * HID, HID, KVN);
    transpose_half_kernel<<<dim3(HID / 32, ODIM / 32), dim3(32, 8)>>>(Wo, p_wot, ODIM, HID);

    // 1) Fused QG + KV projection (round-10 BK=32 GEMM)
    cudaFuncSetAttribute(hgemm_kernel, cudaFuncAttributeMaxDynamicSharedMemorySize, TG_SMEM);
    hgemm_kernel<<<dim3(QGN / 128 + 2*KVN / 128, MM / 256), 256, TG_SMEM>>>(
        p_hs, p_wqt, p_qg, QGN, p_wkvt, p_kv, 2*KVN, HID, QGN / 128);

    // 2) RMSNorm + RoPE + V transpose
    qkv_post_kernel<<<MM * 20 / 8, 256>>>(cosp, sinp, qw, kw);

    // 3) Flash attention + gate (heavy q-tiles in wave 1, masked-warp skip)
    cudaFuncSetAttribute(flash_kernel, cudaFuncAttributeMaxDynamicSharedMemorySize, FL_SMEM);
    flash_kernel<<<dim3(BB * NH, SS / 128), 256, FL_SMEM>>>();

    // 4) Output projection
    hgemm_kernel<<<dim3(HID / 128, MM / 256), 256, TG_SMEM>>>(
        p_attn, p_wot, out, HID, p_wot, out, HID, ODIM, HID / 128);
}

// round 13
// speedup vs baseline: 1.4172x; 1.0381x over previous
#include <cuda_runtime.h>
#include <cuda_fp16.h>
#include <math.h>

// Problem constants
#define BB 2
#define SS 2048
#define HID 2048
#define NH 16
#define NKVH 2
#define DH 256
#define ROT 64
#define MM (BB*SS)          // 4096 tokens
#define QGN (NH*DH*2)       // 8192
#define KVN (NKVH*DH)       // 512
#define ODIM (NH*DH)        // 4096

// Scratch (device globals)
__device__ __half g_hs  [(size_t)MM * HID];
__device__ __half g_wqt [(size_t)QGN * HID];
__device__ __half g_wkvt[(size_t)(2*KVN) * HID];
__device__ __half g_wot [(size_t)HID * ODIM];
__device__ __half g_qg  [(size_t)MM * QGN];          // fp16 now
__device__ __half g_kv  [(size_t)MM * 2*KVN];        // fp16 now
__device__ __half g_q   [(size_t)BB * NH  * SS * DH];
__device__ __half g_kr  [(size_t)BB * NKVH * SS * DH];
__device__ __half g_vr  [(size_t)BB * NKVH * DH * SS];   // [b][kvh][d][s]
__device__ __half g_attn[(size_t)MM * ODIM];

// ---------------- device helpers ----------------
__device__ __forceinline__ unsigned smem_u32(const void* p) {
    unsigned a;
    asm("{ .reg .u64 t; cvta.to.shared.u64 t, %1; cvt.u32.u64 %0, t; }" : "=r"(a) : "l"(p));
    return a;
}
__device__ __forceinline__ void mma_f16(float c[4], const unsigned a[4], const unsigned* b) {
    asm volatile(
        "mma.sync.aligned.m16n8k16.row.col.f32.f16.f16.f32 "
        "{%0,%1,%2,%3}, {%4,%5,%6,%7}, {%8,%9}, {%0,%1,%2,%3};\n"
        : "+f"(c[0]), "+f"(c[1]), "+f"(c[2]), "+f"(c[3])
        : "r"(a[0]), "r"(a[1]), "r"(a[2]), "r"(a[3]), "r"(b[0]), "r"(b[1]));
}
__device__ __forceinline__ void ldsm4(unsigned r[4], const __half* p) {
    unsigned a = smem_u32(p);
    asm volatile("ldmatrix.sync.aligned.m8n8.x4.shared.b16 {%0,%1,%2,%3}, [%4];\n"
                 : "=r"(r[0]), "=r"(r[1]), "=r"(r[2]), "=r"(r[3]) : "r"(a));
}
__device__ __forceinline__ void cp16(void* dst, const void* src) {
    unsigned d = (unsigned)__cvta_generic_to_shared(dst);
    asm volatile("cp.async.cg.shared.global [%0], [%1], 16;\n" :: "r"(d), "l"(src));
}
__device__ __forceinline__ void cp_commit() { asm volatile("cp.async.commit_group;\n"); }
__device__ __forceinline__ unsigned pack_h2(float a, float b) {
    __half2 h = __floats2half2_rn(a, b);
    return *(unsigned*)&h;
}

// ---------------------------------------------------------------------------
// Prep: fp32 -> fp16
// ---------------------------------------------------------------------------
__global__ __launch_bounds__(256) void half_kernel(const float* __restrict__ src,
                                                   __half* __restrict__ dst, int n8)
{
    for (int i = blockIdx.x * 256 + threadIdx.x; i < n8; i += gridDim.x * 256) {
        float4 v0 = ((const float4*)src)[i * 2];
        float4 v1 = ((const float4*)src)[i * 2 + 1];
        __half2 h[4];
        h[0] = __floats2half2_rn(v0.x, v0.y);
        h[1] = __floats2half2_rn(v0.z, v0.w);
        h[2] = __floats2half2_rn(v1.x, v1.y);
        h[3] = __floats2half2_rn(v1.z, v1.w);
        ((uint4*)dst)[i] = *(uint4*)h;
    }
}

// ---------------------------------------------------------------------------
// Prep: transpose + fp16. src [R][C] fp32 -> dst [C][R] fp16.
// ---------------------------------------------------------------------------
__global__ __launch_bounds__(256) void transpose_half_kernel(
    const float* __restrict__ src, __half* __restrict__ dst, int R, int C)
{
    __shared__ float t[32][33];
    const int x = blockIdx.x * 32 + threadIdx.x;
    const int y0 = blockIdx.y * 32;
#pragma unroll
    for (int i = 0; i < 32; i += 8)
        t[threadIdx.y + i][threadIdx.x] = src[(size_t)(y0 + threadIdx.y + i) * C + x];
    __syncthreads();
    const int nx = blockIdx.y * 32 + threadIdx.x;
    const int ny0 = blockIdx.x * 32;
#pragma unroll
    for (int i = 0; i < 32; i += 8)
        dst[(size_t)(ny0 + threadIdx.y + i) * R + nx] =
            __float2half(t[threadIdx.x][threadIdx.y + i]);
}

// ---------------------------------------------------------------------------
// fp16 GEMM (3-stage cp.async, BK=32), DUAL-OUTPUT, selectable output dtype:
// half_out!=0 -> C* treated as __half*, else float*.
// CTA tile 256x128, 8 warps (4x2), warp 64x64.
// ---------------------------------------------------------------------------
#define GS_STR 40
#define TG_SMEM ((3*256*GS_STR + 3*128*GS_STR) * (int)sizeof(__half))

__global__ __launch_bounds__(256, 1) void hgemm_kernel(
    const __half* __restrict__ A,
    const __half* __restrict__ B1t, void* __restrict__ C1, int N1,
    const __half* __restrict__ B2t, void* __restrict__ C2, int N2,
    int K, int nbx1, int half_out)
{
    extern __shared__ __half hsm[];
    __half* As = hsm;
    __half* Bs = hsm + 3 * 256 * GS_STR;

    const int tid = threadIdx.x;
    int bx = blockIdx.x;
    const int by = blockIdx.y;
    const __half* Bt; void* C; int N;
    if (bx < nbx1) { Bt = B1t; C = C1; N = N1; }
    else           { bx -= nbx1; Bt = B2t; C = C2; N = N2; }

    const int lane = tid & 31;
    const int g = lane >> 2, t = lane & 3;
    const int wid = tid >> 5;
    const int m0 = (wid >> 1) * 64;
    const int n0 = (wid & 1) * 64;

    const int a_row = ((lane >> 3) & 1) * 8 + (lane & 7);
    const int a_kh  = (lane >> 4) * 8;
    const int b_row = ((lane >> 4) & 1) * 8 + (lane & 7);
    const int b_kh  = ((lane >> 3) & 1) * 8;

    const int nk = K >> 5;

    auto issue = [&](int st, int k0) {
        __half* Ad = As + (size_t)st * 256 * GS_STR;
        __half* Bd = Bs + (size_t)st * 128 * GS_STR;
#pragma unroll
        for (int it = 0; it < 4; it++) {
            int idx = tid + it * 256;
            int row = idx >> 2;
            int ch  = (idx & 3) * 8;
            cp16(Ad + row * GS_STR + ch, A + (size_t)(by * 256 + row) * K + k0 + ch);
        }
#pragma unroll
        for (int it = 0; it < 2; it++) {
            int idx = tid + it * 256;
            int row = idx >> 2;
            int ch  = (idx & 3) * 8;
            cp16(Bd + row * GS_STR + ch, Bt + (size_t)(bx * 128 + row) * K + k0 + ch);
        }
        cp_commit();
    };

    issue(0, 0);
    if (nk > 1) issue(1, 32);
    if (nk > 2) issue(2, 64);

    float acc[4][8][4];
#pragma unroll
    for (int mt = 0; mt < 4; mt++)
#pragma unroll
        for (int nt = 0; nt < 8; nt++)
#pragma unroll
            for (int r = 0; r < 4; r++) acc[mt][nt][r] = 0.f;

    for (int i = 0; i < nk; i++) {
        const int st = i % 3;
        __half* Ad = As + (size_t)st * 256 * GS_STR;
        __half* Bd = Bs + (size_t)st * 128 * GS_STR;
        if (i + 2 < nk)      asm volatile("cp.async.wait_group 2;\n");
        else if (i + 1 < nk) asm volatile("cp.async.wait_group 1;\n");
        else                 asm volatile("cp.async.wait_group 0;\n");
        __syncthreads();

#pragma unroll
        for (int kk = 0; kk < 32; kk += 16) {
            unsigned a[4][4], bfr[4][4];
#pragma unroll
            for (int mt = 0; mt < 4; mt++)
                ldsm4(a[mt], Ad + (m0 + mt * 16 + a_row) * GS_STR + kk + a_kh);
#pragma unroll
            for (int p = 0; p < 4; p++)
                ldsm4(bfr[p], Bd + (n0 + p * 16 + b_row) * GS_STR + kk + b_kh);
#pragma unroll
            for (int mt = 0; mt < 4; mt++)
#pragma unroll
                for (int nt = 0; nt < 8; nt++)
                    mma_f16(acc[mt][nt], a[mt], &bfr[nt >> 1][(nt & 1) * 2]);
        }
        __syncthreads();
        if (i + 3 < nk) issue(st, (i + 3) * 32);
    }

    if (half_out) {
        __half* Ch = (__half*)C;
#pragma unroll
        for (int mt = 0; mt < 4; mt++) {
            const int r = by * 256 + m0 + mt * 16 + g;
#pragma unroll
            for (int nt = 0; nt < 8; nt++) {
                const int c = bx * 128 + n0 + nt * 8 + 2 * t;
                *(__half2*)(Ch + (size_t)r * N + c) =
                    __floats2half2_rn(acc[mt][nt][0], acc[mt][nt][1]);
                *(__half2*)(Ch + (size_t)(r + 8) * N + c) =
                    __floats2half2_rn(acc[mt][nt][2], acc[mt][nt][3]);
            }
        }
    } else {
        float* Cf = (float*)C;
#pragma unroll
        for (int mt = 0; mt < 4; mt++) {
            const int r = by * 256 + m0 + mt * 16 + g;
#pragma unroll
            for (int nt = 0; nt < 8; nt++) {
                const int c = bx * 128 + n0 + nt * 8 + 2 * t;
                *(float2*)(Cf + (size_t)r * N + c)       = make_float2(acc[mt][nt][0], acc[mt][nt][1]);
                *(float2*)(Cf + (size_t)(r + 8) * N + c) = make_float2(acc[mt][nt][2], acc[mt][nt][3]);
            }
        }
    }
}

// ---------------------------------------------------------------------------
// Post-process v3: one WARP per (token, unit); fp16 inputs. Shfl reductions.
// ---------------------------------------------------------------------------
__global__ __launch_bounds__(256) void qkv_post_kernel(
    const float* __restrict__ cosp, const float* __restrict__ sinp,
    const float* __restrict__ qw, const float* __restrict__ kw)
{
    const int wi = blockIdx.x * 8 + (threadIdx.x >> 5);
    const int lane = threadIdx.x & 31;
    const int token = wi / 20;
    const int unit  = wi % 20;
    const int b = token >> 11;
    const int s = token & 2047;
    const int d0 = lane * 8;

    if (unit >= 18) {
        const int kvh = unit - 18;
        // straight fp16 copy with transpose
        uint4 raw = *(const uint4*)(g_kv + (size_t)token * (2*KVN) + 512 + kvh * 256 + d0);
        const __half* hv = (const __half*)&raw;
        __half* dst = g_vr + (((size_t)b * NKVH + kvh) * DH + d0) * SS + s;
#pragma unroll
        for (int j = 0; j < 8; j++) dst[j * SS] = hv[j];
        return;
    }

    const __half* src;
    const float* w;
    if (unit < 16) { src = g_qg + (size_t)token * QGN + unit * 512 + d0; w = qw + d0; }
    else           { src = g_kv + (size_t)token * (2*KVN) + (unit - 16) * 256 + d0; w = kw + d0; }

    uint4 raw = *(const uint4*)src;
    const __half* hx = (const __half*)&raw;
    float x[8];
#pragma unroll
    for (int j = 0; j < 8; j++) x[j] = __half2float(hx[j]);

    float ss = 0.f;
#pragma unroll
    for (int j = 0; j < 8; j++) ss += x[j] * x[j];
#pragma unroll
    for (int o = 16; o; o >>= 1) ss += __shfl_xor_sync(0xffffffffu, ss, o);
    const float rsn = rsqrtf(ss * (1.0f / 256.0f) + 1e-6f);

    float xn[8];
#pragma unroll
    for (int j = 0; j < 8; j++) xn[j] = x[j] * rsn * (1.0f + w[j]);

    float rot[8];
#pragma unroll
    for (int j = 0; j < 8; j++) rot[j] = __shfl_xor_sync(0xffffffffu, xn[j], 4);
    if (lane < 8) {
        float cs[8], sn[8];
        *(float4*)(cs)     = *(const float4*)(cosp + (size_t)token * ROT + d0);
        *(float4*)(cs + 4) = *(const float4*)(cosp + (size_t)token * ROT + d0 + 4);
        *(float4*)(sn)     = *(const float4*)(sinp + (size_t)token * ROT + d0);
        *(float4*)(sn + 4) = *(const float4*)(sinp + (size_t)token * ROT + d0 + 4);
#pragma unroll
        for (int j = 0; j < 8; j++) {
            float rr = (lane & 4) ? rot[j] : -rot[j];
            xn[j] = xn[j] * cs[j] + rr * sn[j];
        }
    }

    __half2 h[4];
    if (unit < 16) {
#pragma unroll
        for (int j = 0; j < 4; j++)
            h[j] = __floats2half2_rn(xn[2*j] * 0.0625f, xn[2*j+1] * 0.0625f);
        *(uint4*)(g_q + (((size_t)b * NH + unit) * SS + s) * DH + d0) = *(uint4*)h;
    } else {
#pragma unroll
        for (int j = 0; j < 4; j++)
            h[j] = __floats2half2_rn(xn[2*j], xn[2*j+1]);
        *(uint4*)(g_kr + (((size_t)b * NKVH + (unit - 16)) * SS + s) * DH + d0) = *(uint4*)h;
    }
}

// ---------------------------------------------------------------------------
// Flash attention v8: warp-autonomous 16-row warps, register-resident P,
// K AND V double-buffered (2 syncs + 1 wait per iteration). Heavy q-tiles
// first; fully-masked warp tiles skipped. fp16 gate.
// ---------------------------------------------------------------------------
#define QS_STR 264
#define KS_STR 264
#define VS_STR 72
#define FL_SMEM ((128*QS_STR + 2*64*KS_STR + 2*256*VS_STR) * 2)

__global__ __launch_bounds__(256, 1) void flash_kernel()
{
    extern __shared__ __half smh[];
    __half* Qs = smh;                        // [128][QS_STR]
    __half* Ks = Qs + 128 * QS_STR;          // [2][64][KS_STR]
    __half* Vs = Ks + 2 * 64 * KS_STR;       // [2][256][VS_STR] ([d][key])

    const int tid = threadIdx.x;
    const int lane = tid & 31;
    const int g = lane >> 2, t = lane & 3;
    const int w = tid >> 5;
    const int rb = w * 16;

    const int a_row = ((lane >> 3) & 1) * 8 + (lane & 7);
    const int a_kh  = (lane >> 4) * 8;
    const int b_row = ((lane >> 4) & 1) * 8 + (lane & 7);
    const int b_kh  = ((lane >> 3) & 1) * 8;

    const int qt = (int)gridDim.y - 1 - (int)blockIdx.y;   // heavy first
    const int b  = blockIdx.x >> 4;
    const int h  = blockIdx.x & 15;
    const int kvh = h >> 3;
    const int q0 = qt * 128;

    const __half* Qp  = g_q  + (((size_t)b * NH + h) * SS + q0) * DH;
    const __half* Kp  = g_kr + ((size_t)b * NKVH + kvh) * SS * DH;
    const __half* VpT = g_vr + ((size_t)b * NKVH + kvh) * DH * SS;

    auto issueKV = [&](int kt, int st) {
        const __half* Kt = Kp + (size_t)(kt * 64) * DH;
        __half* Kd = Ks + st * 64 * KS_STR;
        __half* Vd = Vs + st * 256 * VS_STR;
#pragma unroll
        for (int it = 0; it < 8; it++) {
            const int idx = tid + it * 256;
            const int key = idx >> 5;
            const int col = (idx & 31) * 8;
            cp16(Kd + key * KS_STR + col, Kt + (size_t)key * DH + col);
            const int dl = idx >> 3;
            const int kc = (idx & 7) * 8;
            cp16(Vd + dl * VS_STR + kc, VpT + (size_t)dl * SS + kt * 64 + kc);
        }
        cp_commit();
    };

    // Q resident
#pragma unroll
    for (int it = 0; it < 16; it++) {
        const int idx = tid + it * 256;
        const int r = idx >> 5;
        const int c = (idx & 31) * 8;
        *(uint4*)&Qs[r * QS_STR + c] = *(const uint4*)(Qp + (size_t)r * DH + c);
    }

    float o[32][4];
    float m[2], l[2];
#pragma unroll
    for (int cc = 0; cc < 32; cc++)
#pragma unroll
        for (int r = 0; r < 4; r++) o[cc][r] = 0.f;
    m[0] = m[1] = -1e30f; l[0] = l[1] = 0.f;

    const int ktmax = 2 * qt + 1;

    issueKV(0, 0);
    issueKV(1, 1);   // ktmax >= 1 always

    for (int kt = 0; kt <= ktmax; kt++) {
        const int st = kt & 1;
        if (kt + 1 <= ktmax) asm volatile("cp.async.wait_group 1;\n");
        else                 asm volatile("cp.async.wait_group 0;\n");
        __syncthreads();   // stage st landed; everyone aligned

        const bool active = (kt * 64 <= q0 + rb + 15);

        float s[8][4];
        if (active) {
            const __half* Kd = Ks + st * 64 * KS_STR;
            const __half* Vd = Vs + st * 256 * VS_STR;
#pragma unroll
            for (int nt = 0; nt < 8; nt++)
#pragma unroll
                for (int r = 0; r < 4; r++) s[nt][r] = 0.f;

#pragma unroll
            for (int kk = 0; kk < 256; kk += 16) {
                unsigned a[4], bq[4][4];
                ldsm4(a, Qs + (rb + a_row) * QS_STR + kk + a_kh);
#pragma unroll
                for (int p = 0; p < 4; p++)
                    ldsm4(bq[p], Kd + (p * 16 + b_row) * KS_STR + kk + b_kh);
#pragma unroll
                for (int nt = 0; nt < 8; nt++)
                    mma_f16(s[nt], a, &bq[nt >> 1][(nt & 1) * 2]);
            }

            if (kt >= 2 * qt) {
#pragma unroll
                for (int nt = 0; nt < 8; nt++)
#pragma unroll
                    for (int r = 0; r < 4; r++) {
                        const int row = q0 + rb + (r >> 1) * 8 + g;
                        const int col = kt * 64 + nt * 8 + 2 * t + (r & 1);
                        if (col > row) s[nt][r] = -1e30f;
                    }
            }

            float al[2];
#pragma unroll
            for (int hh = 0; hh < 2; hh++) {
                float v = -1e30f;
#pragma unroll
                for (int nt = 0; nt < 8; nt++)
                    v = fmaxf(v, fmaxf(s[nt][hh * 2], s[nt][hh * 2 + 1]));
                v = fmaxf(v, __shfl_xor_sync(0xffffffffu, v, 1));
                v = fmaxf(v, __shfl_xor_sync(0xffffffffu, v, 2));
                float mn = fmaxf(m[hh], v);
                al[hh] = __expf(m[hh] - mn);
                m[hh] = mn;
                float rs = 0.f;
#pragma unroll
                for (int nt = 0; nt < 8; nt++) {
                    float p0 = __expf(s[nt][hh * 2]     - mn);
                    float p1 = __expf(s[nt][hh * 2 + 1] - mn);
                    s[nt][hh * 2] = p0; s[nt][hh * 2 + 1] = p1;
                    rs += p0 + p1;
                }
                rs += __shfl_xor_sync(0xffffffffu, rs, 1);
                rs += __shfl_xor_sync(0xffffffffu, rs, 2);
                l[hh] = l[hh] * al[hh] + rs;
#pragma unroll
                for (int cc = 0; cc < 32; cc++) {
                    o[cc][hh * 2]     *= al[hh];
                    o[cc][hh * 2 + 1] *= al[hh];
                }
            }

            // ---- O += P V : P C-frags pack directly into A-frags ----
#pragma unroll
            for (int kk4 = 0; kk4 < 4; kk4++) {
                unsigned pa[4];
                pa[0] = pack_h2(s[2*kk4][0],   s[2*kk4][1]);
                pa[1] = pack_h2(s[2*kk4][2],   s[2*kk4][3]);
                pa[2] = pack_h2(s[2*kk4+1][0], s[2*kk4+1][1]);
                pa[3] = pack_h2(s[2*kk4+1][2], s[2*kk4+1][3]);
#pragma unroll
                for (int half = 0; half < 2; half++) {
                    unsigned bv[8][4];
#pragma unroll
                    for (int p = 0; p < 8; p++)
                        ldsm4(bv[p], Vd + (half * 128 + p * 16 + b_row) * VS_STR + kk4 * 16 + b_kh);
#pragma unroll
                    for (int nt = 0; nt < 16; nt++)
                        mma_f16(o[half * 16 + nt], pa, &bv[nt >> 1][(nt & 1) * 2]);
                }
            }
        }

        __syncthreads();   // all warps done reading stage st
        if (kt + 2 <= ktmax) issueKV(kt + 2, st);
    }

    // ---- epilogue: /l, * sigmoid(gate) ----
#pragma unroll
    for (int hh = 0; hh < 2; hh++) {
        const int row = q0 + rb + hh * 8 + g;
        const size_t token = (size_t)b * SS + row;
        const float inv = 1.f / l[hh];
#pragma unroll
        for (int cc = 0; cc < 32; cc++) {
            const int col = cc * 8 + 2 * t;
            __half2 gt2 = *(const __half2*)(g_qg + token * QGN + h * 512 + 256 + col);
            float2 gt = __half22float2(gt2);
            float ox = o[cc][hh * 2]     * inv / (1.f + __expf(-gt.x));
            float oy = o[cc][hh * 2 + 1] * inv / (1.f + __expf(-gt.y));
            *(__half2*)(g_attn + token * ODIM + h * 256 + col) =
                __floats2half2_rn(ox, oy);
        }
    }
}

// ---------------------------------------------------------------------------
extern "C" void kernel_launch(void* const* d_in, const int* in_sizes, int n_in,
                              void* d_out, int out_size)
{
    (void)in_sizes; (void)n_in; (void)out_size;
    const float* hs   = (const float*)d_in[0];
    const float* cosp = (const float*)d_in[1];
    const float* sinp = (const float*)d_in[2];
    const float* Wq   = (const float*)d_in[3];
    const float* Wk   = (const float*)d_in[4];
    const float* Wv   = (const float*)d_in[5];
    const float* Wo   = (const float*)d_in[6];
    const float* qw   = (const float*)d_in[7];
    const float* kw   = (const float*)d_in[8];
    float* out = (float*)d_out;

    __half *p_hs, *p_wqt, *p_wkvt, *p_wot, *p_attn, *p_qg, *p_kv;
    cudaGetSymbolAddress((void**)&p_hs,   g_hs);
    cudaGetSymbolAddress((void**)&p_wqt,  g_wqt);
    cudaGetSymbolAddress((void**)&p_wkvt, g_wkvt);
    cudaGetSymbolAddress((void**)&p_wot,  g_wot);
    cudaGetSymbolAddress((void**)&p_qg,   g_qg);
    cudaGetSymbolAddress((void**)&p_kv,   g_kv);
    cudaGetSymbolAddress((void**)&p_attn, g_attn);

    // 0) Prep
    half_kernel<<<1024, 256>>>(hs, p_hs, MM * HID / 8);
    transpose_half_kernel<<<dim3(QGN / 32, HID / 32), dim3(32, 8)>>>(Wq, p_wqt, HID, QGN);
    transpose_half_kernel<<<dim3(KVN / 32, HID / 32), dim3(32, 8)>>>(Wk, p_wkvt, HID, KVN);
    transpose_half_kernel<<<dim3(KVN / 32, HID / 32), dim3(32, 8)>>>(Wv, p_wkvt + (size_t)KVN * HID, HID, KVN);
    transpose_half_kernel<<<dim3(HID / 32, ODIM / 32), dim3(32, 8)>>>(Wo, p_wot, ODIM, HID);

    // 1) Fused QG + KV projection (fp16 outputs)
    cudaFuncSetAttribute(hgemm_kernel, cudaFuncAttributeMaxDynamicSharedMemorySize, TG_SMEM);
    hgemm_kernel<<<dim3(QGN / 128 + 2*KVN / 128, MM / 256), 256, TG_SMEM>>>(
        p_hs, p_wqt, p_qg, QGN, p_wkvt, p_kv, 2*KVN, HID, QGN / 128, 1);

    // 2) RMSNorm + RoPE + V transpose
    qkv_post_kernel<<<MM * 20 / 8, 256>>>(cosp, sinp, qw, kw);

    // 3) Flash attention + gate (K+V double-buffered)
    cudaFuncSetAttribute(flash_kernel, cudaFuncAttributeMaxDynamicSharedMemorySize, FL_SMEM);
    flash_kernel<<<dim3(BB * NH, SS / 128), 256, FL_SMEM>>>();

    // 4) Output projection (fp32 output)
    hgemm_kernel<<<dim3(HID / 128, MM / 256), 256, TG_SMEM>>>(
        p_attn, p_wot, out, HID, p_wot, out, HID, ODIM, HID / 128, 0);
}

// round 14
// speedup vs baseline: 1.5185x; 1.0715x over previous
#include <cuda_runtime.h>
#include <cuda_fp16.h>
#include <math.h>

// Problem constants
#define BB 2
#define SS 2048
#define HID 2048
#define NH 16
#define NKVH 2
#define DH 256
#define ROT 64
#define MM (BB*SS)          // 4096 tokens
#define QGN (NH*DH*2)       // 8192
#define KVN (NKVH*DH)       // 512
#define ODIM (NH*DH)        // 4096

// Scratch (device globals)
__device__ __half g_hs  [(size_t)MM * HID];
__device__ __half g_wqt [(size_t)QGN * HID];
__device__ __half g_wkvt[(size_t)(2*KVN) * HID];
__device__ __half g_wot [(size_t)HID * ODIM];
__device__ __half g_qg  [(size_t)MM * QGN];          // fp16
__device__ __half g_kv  [(size_t)MM * 2*KVN];        // fp16
__device__ __half g_q   [(size_t)BB * NH  * SS * DH];
__device__ __half g_kr  [(size_t)BB * NKVH * SS * DH];
__device__ __half g_vr  [(size_t)BB * NKVH * DH * SS];   // [b][kvh][d][s]
__device__ __half g_attn[(size_t)MM * ODIM];

// ---------------- device helpers ----------------
__device__ __forceinline__ unsigned smem_u32(const void* p) {
    unsigned a;
    asm("{ .reg .u64 t; cvta.to.shared.u64 t, %1; cvt.u32.u64 %0, t; }" : "=r"(a) : "l"(p));
    return a;
}
__device__ __forceinline__ void mma_f16(float c[4], const unsigned a[4], const unsigned* b) {
    asm volatile(
        "mma.sync.aligned.m16n8k16.row.col.f32.f16.f16.f32 "
        "{%0,%1,%2,%3}, {%4,%5,%6,%7}, {%8,%9}, {%0,%1,%2,%3};\n"
        : "+f"(c[0]), "+f"(c[1]), "+f"(c[2]), "+f"(c[3])
        : "r"(a[0]), "r"(a[1]), "r"(a[2]), "r"(a[3]), "r"(b[0]), "r"(b[1]));
}
__device__ __forceinline__ void ldsm4(unsigned r[4], const __half* p) {
    unsigned a = smem_u32(p);
    asm volatile("ldmatrix.sync.aligned.m8n8.x4.shared.b16 {%0,%1,%2,%3}, [%4];\n"
                 : "=r"(r[0]), "=r"(r[1]), "=r"(r[2]), "=r"(r[3]) : "r"(a));
}
__device__ __forceinline__ void cp16(void* dst, const void* src) {
    unsigned d = (unsigned)__cvta_generic_to_shared(dst);
    asm volatile("cp.async.cg.shared.global [%0], [%1], 16;\n" :: "r"(d), "l"(src));
}
__device__ __forceinline__ void cp_commit() { asm volatile("cp.async.commit_group;\n"); }
__device__ __forceinline__ unsigned pack_h2(float a, float b) {
    __half2 h = __floats2half2_rn(a, b);
    return *(unsigned*)&h;
}

// ---------------------------------------------------------------------------
// Prep: fp32 -> fp16
// ---------------------------------------------------------------------------
__global__ __launch_bounds__(256) void half_kernel(const float* __restrict__ src,
                                                   __half* __restrict__ dst, int n8)
{
    for (int i = blockIdx.x * 256 + threadIdx.x; i < n8; i += gridDim.x * 256) {
        float4 v0 = ((const float4*)src)[i * 2];
        float4 v1 = ((const float4*)src)[i * 2 + 1];
        __half2 h[4];
        h[0] = __floats2half2_rn(v0.x, v0.y);
        h[1] = __floats2half2_rn(v0.z, v0.w);
        h[2] = __floats2half2_rn(v1.x, v1.y);
        h[3] = __floats2half2_rn(v1.z, v1.w);
        ((uint4*)dst)[i] = *(uint4*)h;
    }
}

// ---------------------------------------------------------------------------
// Prep: transpose + fp16. src [R][C] fp32 -> dst [C][R] fp16.
// ---------------------------------------------------------------------------
__global__ __launch_bounds__(256) void transpose_half_kernel(
    const float* __restrict__ src, __half* __restrict__ dst, int R, int C)
{
    __shared__ float t[32][33];
    const int x = blockIdx.x * 32 + threadIdx.x;
    const int y0 = blockIdx.y * 32;
#pragma unroll
    for (int i = 0; i < 32; i += 8)
        t[threadIdx.y + i][threadIdx.x] = src[(size_t)(y0 + threadIdx.y + i) * C + x];
    __syncthreads();
    const int nx = blockIdx.y * 32 + threadIdx.x;
    const int ny0 = blockIdx.x * 32;
#pragma unroll
    for (int i = 0; i < 32; i += 8)
        dst[(size_t)(ny0 + threadIdx.y + i) * R + nx] =
            __float2half(t[threadIdx.x][threadIdx.y + i]);
}

// ---------------------------------------------------------------------------
// fp16 GEMM v9: CTA tile 128x128 (2 CTAs/SM), BK=32, 3-stage cp.async,
// 8 warps (2x4... -> 4 wm x 2 wn? use 2x4): warps (wm 0..3 x wn 0..1),
// warp tile 32x64. DUAL-OUTPUT + selectable output dtype.
// ---------------------------------------------------------------------------
#define GS_STR 40
#define TG_SMEM ((3*128*GS_STR + 3*128*GS_STR) * (int)sizeof(__half))

__global__ __launch_bounds__(256, 2) void hgemm_kernel(
    const __half* __restrict__ A,
    const __half* __restrict__ B1t, void* __restrict__ C1, int N1,
    const __half* __restrict__ B2t, void* __restrict__ C2, int N2,
    int K, int nbx1, int half_out)
{
    extern __shared__ __half hsm[];
    __half* As = hsm;                        // [3][128][GS_STR]
    __half* Bs = hsm + 3 * 128 * GS_STR;     // [3][128][GS_STR]

    const int tid = threadIdx.x;
    int bx = blockIdx.x;
    const int by = blockIdx.y;
    const __half* Bt; void* C; int N;
    if (bx < nbx1) { Bt = B1t; C = C1; N = N1; }
    else           { bx -= nbx1; Bt = B2t; C = C2; N = N2; }

    const int lane = tid & 31;
    const int g = lane >> 2, t = lane & 3;
    const int wid = tid >> 5;
    const int m0 = (wid >> 1) * 32;
    const int n0 = (wid & 1) * 64;

    const int a_row = ((lane >> 3) & 1) * 8 + (lane & 7);
    const int a_kh  = (lane >> 4) * 8;
    const int b_row = ((lane >> 4) & 1) * 8 + (lane & 7);
    const int b_kh  = ((lane >> 3) & 1) * 8;

    const int nk = K >> 5;

    auto issue = [&](int st, int k0) {
        __half* Ad = As + (size_t)st * 128 * GS_STR;
        __half* Bd = Bs + (size_t)st * 128 * GS_STR;
#pragma unroll
        for (int it = 0; it < 2; it++) {
            int idx = tid + it * 256;        // 0..511
            int row = idx >> 2;              // 0..127
            int ch  = (idx & 3) * 8;
            cp16(Ad + row * GS_STR + ch, A + (size_t)(by * 128 + row) * K + k0 + ch);
            cp16(Bd + row * GS_STR + ch, Bt + (size_t)(bx * 128 + row) * K + k0 + ch);
        }
        cp_commit();
    };

    issue(0, 0);
    if (nk > 1) issue(1, 32);
    if (nk > 2) issue(2, 64);

    float acc[2][8][4];
#pragma unroll
    for (int mt = 0; mt < 2; mt++)
#pragma unroll
        for (int nt = 0; nt < 8; nt++)
#pragma unroll
            for (int r = 0; r < 4; r++) acc[mt][nt][r] = 0.f;

    for (int i = 0; i < nk; i++) {
        const int st = i % 3;
        __half* Ad = As + (size_t)st * 128 * GS_STR;
        __half* Bd = Bs + (size_t)st * 128 * GS_STR;
        if (i + 2 < nk)      asm volatile("cp.async.wait_group 2;\n");
        else if (i + 1 < nk) asm volatile("cp.async.wait_group 1;\n");
        else                 asm volatile("cp.async.wait_group 0;\n");
        __syncthreads();

#pragma unroll
        for (int kk = 0; kk < 32; kk += 16) {
            unsigned a[2][4], bfr[4][4];
#pragma unroll
            for (int mt = 0; mt < 2; mt++)
                ldsm4(a[mt], Ad + (m0 + mt * 16 + a_row) * GS_STR + kk + a_kh);
#pragma unroll
            for (int p = 0; p < 4; p++)
                ldsm4(bfr[p], Bd + (n0 + p * 16 + b_row) * GS_STR + kk + b_kh);
#pragma unroll
            for (int mt = 0; mt < 2; mt++)
#pragma unroll
                for (int nt = 0; nt < 8; nt++)
                    mma_f16(acc[mt][nt], a[mt], &bfr[nt >> 1][(nt & 1) * 2]);
        }
        __syncthreads();
        if (i + 3 < nk) issue(st, (i + 3) * 32);
    }

    if (half_out) {
        __half* Ch = (__half*)C;
#pragma unroll
        for (int mt = 0; mt < 2; mt++) {
            const int r = by * 128 + m0 + mt * 16 + g;
#pragma unroll
            for (int nt = 0; nt < 8; nt++) {
                const int c = bx * 128 + n0 + nt * 8 + 2 * t;
                *(__half2*)(Ch + (size_t)r * N + c) =
                    __floats2half2_rn(acc[mt][nt][0], acc[mt][nt][1]);
                *(__half2*)(Ch + (size_t)(r + 8) * N + c) =
                    __floats2half2_rn(acc[mt][nt][2], acc[mt][nt][3]);
            }
        }
    } else {
        float* Cf = (float*)C;
#pragma unroll
        for (int mt = 0; mt < 2; mt++) {
            const int r = by * 128 + m0 + mt * 16 + g;
#pragma unroll
            for (int nt = 0; nt < 8; nt++) {
                const int c = bx * 128 + n0 + nt * 8 + 2 * t;
                *(float2*)(Cf + (size_t)r * N + c)       = make_float2(acc[mt][nt][0], acc[mt][nt][1]);
                *(float2*)(Cf + (size_t)(r + 8) * N + c) = make_float2(acc[mt][nt][2], acc[mt][nt][3]);
            }
        }
    }
}

// ---------------------------------------------------------------------------
// Post-process v3: one WARP per (token, unit); fp16 inputs. Shfl reductions.
// ---------------------------------------------------------------------------
__global__ __launch_bounds__(256) void qkv_post_kernel(
    const float* __restrict__ cosp, const float* __restrict__ sinp,
    const float* __restrict__ qw, const float* __restrict__ kw)
{
    const int wi = blockIdx.x * 8 + (threadIdx.x >> 5);
    const int lane = threadIdx.x & 31;
    const int token = wi / 20;
    const int unit  = wi % 20;
    const int b = token >> 11;
    const int s = token & 2047;
    const int d0 = lane * 8;

    if (unit >= 18) {
        const int kvh = unit - 18;
        uint4 raw = *(const uint4*)(g_kv + (size_t)token * (2*KVN) + 512 + kvh * 256 + d0);
        const __half* hv = (const __half*)&raw;
        __half* dst = g_vr + (((size_t)b * NKVH + kvh) * DH + d0) * SS + s;
#pragma unroll
        for (int j = 0; j < 8; j++) dst[j * SS] = hv[j];
        return;
    }

    const __half* src;
    const float* w;
    if (unit < 16) { src = g_qg + (size_t)token * QGN + unit * 512 + d0; w = qw + d0; }
    else           { src = g_kv + (size_t)token * (2*KVN) + (unit - 16) * 256 + d0; w = kw + d0; }

    uint4 raw = *(const uint4*)src;
    const __half* hx = (const __half*)&raw;
    float x[8];
#pragma unroll
    for (int j = 0; j < 8; j++) x[j] = __half2float(hx[j]);

    float ss = 0.f;
#pragma unroll
    for (int j = 0; j < 8; j++) ss += x[j] * x[j];
#pragma unroll
    for (int o = 16; o; o >>= 1) ss += __shfl_xor_sync(0xffffffffu, ss, o);
    const float rsn = rsqrtf(ss * (1.0f / 256.0f) + 1e-6f);

    float xn[8];
#pragma unroll
    for (int j = 0; j < 8; j++) xn[j] = x[j] * rsn * (1.0f + w[j]);

    float rot[8];
#pragma unroll
    for (int j = 0; j < 8; j++) rot[j] = __shfl_xor_sync(0xffffffffu, xn[j], 4);
    if (lane < 8) {
        float cs[8], sn[8];
        *(float4*)(cs)     = *(const float4*)(cosp + (size_t)token * ROT + d0);
        *(float4*)(cs + 4) = *(const float4*)(cosp + (size_t)token * ROT + d0 + 4);
        *(float4*)(sn)     = *(const float4*)(sinp + (size_t)token * ROT + d0);
        *(float4*)(sn + 4) = *(const float4*)(sinp + (size_t)token * ROT + d0 + 4);
#pragma unroll
        for (int j = 0; j < 8; j++) {
            float rr = (lane & 4) ? rot[j] : -rot[j];
            xn[j] = xn[j] * cs[j] + rr * sn[j];
        }
    }

    __half2 h[4];
    if (unit < 16) {
#pragma unroll
        for (int j = 0; j < 4; j++)
            h[j] = __floats2half2_rn(xn[2*j] * 0.0625f, xn[2*j+1] * 0.0625f);
        *(uint4*)(g_q + (((size_t)b * NH + unit) * SS + s) * DH + d0) = *(uint4*)h;
    } else {
#pragma unroll
        for (int j = 0; j < 4; j++)
            h[j] = __floats2half2_rn(xn[2*j], xn[2*j+1]);
        *(uint4*)(g_kr + (((size_t)b * NKVH + (unit - 16)) * SS + s) * DH + d0) = *(uint4*)h;
    }
}

// ---------------------------------------------------------------------------
// Flash attention v8 (round-13): warp-autonomous, register-resident P,
// K+V double-buffered, heavy q-tiles first, masked-warp skip, fp16 gate.
// ---------------------------------------------------------------------------
#define QS_STR 264
#define KS_STR 264
#define VS_STR 72
#define FL_SMEM ((128*QS_STR + 2*64*KS_STR + 2*256*VS_STR) * 2)

__global__ __launch_bounds__(256, 1) void flash_kernel()
{
    extern __shared__ __half smh[];
    __half* Qs = smh;                        // [128][QS_STR]
    __half* Ks = Qs + 128 * QS_STR;          // [2][64][KS_STR]
    __half* Vs = Ks + 2 * 64 * KS_STR;       // [2][256][VS_STR] ([d][key])

    const int tid = threadIdx.x;
    const int lane = tid & 31;
    const int g = lane >> 2, t = lane & 3;
    const int w = tid >> 5;
    const int rb = w * 16;

    const int a_row = ((lane >> 3) & 1) * 8 + (lane & 7);
    const int a_kh  = (lane >> 4) * 8;
    const int b_row = ((lane >> 4) & 1) * 8 + (lane & 7);
    const int b_kh  = ((lane >> 3) & 1) * 8;

    const int qt = (int)gridDim.y - 1 - (int)blockIdx.y;   // heavy first
    const int b  = blockIdx.x >> 4;
    const int h  = blockIdx.x & 15;
    const int kvh = h >> 3;
    const int q0 = qt * 128;

    const __half* Qp  = g_q  + (((size_t)b * NH + h) * SS + q0) * DH;
    const __half* Kp  = g_kr + ((size_t)b * NKVH + kvh) * SS * DH;
    const __half* VpT = g_vr + ((size_t)b * NKVH + kvh) * DH * SS;

    auto issueKV = [&](int kt, int st) {
        const __half* Kt = Kp + (size_t)(kt * 64) * DH;
        __half* Kd = Ks + st * 64 * KS_STR;
        __half* Vd = Vs + st * 256 * VS_STR;
#pragma unroll
        for (int it = 0; it < 8; it++) {
            const int idx = tid + it * 256;
            const int key = idx >> 5;
            const int col = (idx & 31) * 8;
            cp16(Kd + key * KS_STR + col, Kt + (size_t)key * DH + col);
            const int dl = idx >> 3;
            const int kc = (idx & 7) * 8;
            cp16(Vd + dl * VS_STR + kc, VpT + (size_t)dl * SS + kt * 64 + kc);
        }
        cp_commit();
    };

    // Q resident
#pragma unroll
    for (int it = 0; it < 16; it++) {
        const int idx = tid + it * 256;
        const int r = idx >> 5;
        const int c = (idx & 31) * 8;
        *(uint4*)&Qs[r * QS_STR + c] = *(const uint4*)(Qp + (size_t)r * DH + c);
    }

    float o[32][4];
    float m[2], l[2];
#pragma unroll
    for (int cc = 0; cc < 32; cc++)
#pragma unroll
        for (int r = 0; r < 4; r++) o[cc][r] = 0.f;
    m[0] = m[1] = -1e30f; l[0] = l[1] = 0.f;

    const int ktmax = 2 * qt + 1;

    issueKV(0, 0);
    issueKV(1, 1);

    for (int kt = 0; kt <= ktmax; kt++) {
        const int st = kt & 1;
        if (kt + 1 <= ktmax) asm volatile("cp.async.wait_group 1;\n");
        else                 asm volatile("cp.async.wait_group 0;\n");
        __syncthreads();

        const bool active = (kt * 64 <= q0 + rb + 15);

        float s[8][4];
        if (active) {
            const __half* Kd = Ks + st * 64 * KS_STR;
            const __half* Vd = Vs + st * 256 * VS_STR;
#pragma unroll
            for (int nt = 0; nt < 8; nt++)
#pragma unroll
                for (int r = 0; r < 4; r++) s[nt][r] = 0.f;

#pragma unroll
            for (int kk = 0; kk < 256; kk += 16) {
                unsigned a[4], bq[4][4];
                ldsm4(a, Qs + (rb + a_row) * QS_STR + kk + a_kh);
#pragma unroll
                for (int p = 0; p < 4; p++)
                    ldsm4(bq[p], Kd + (p * 16 + b_row) * KS_STR + kk + b_kh);
#pragma unroll
                for (int nt = 0; nt < 8; nt++)
                    mma_f16(s[nt], a, &bq[nt >> 1][(nt & 1) * 2]);
            }

            if (kt >= 2 * qt) {
#pragma unroll
                for (int nt = 0; nt < 8; nt++)
#pragma unroll
                    for (int r = 0; r < 4; r++) {
                        const int row = q0 + rb + (r >> 1) * 8 + g;
                        const int col = kt * 64 + nt * 8 + 2 * t + (r & 1);
                        if (col > row) s[nt][r] = -1e30f;
                    }
            }

            float al[2];
#pragma unroll
            for (int hh = 0; hh < 2; hh++) {
                float v = -1e30f;
#pragma unroll
                for (int nt = 0; nt < 8; nt++)
                    v = fmaxf(v, fmaxf(s[nt][hh * 2], s[nt][hh * 2 + 1]));
                v = fmaxf(v, __shfl_xor_sync(0xffffffffu, v, 1));
                v = fmaxf(v, __shfl_xor_sync(0xffffffffu, v, 2));
                float mn = fmaxf(m[hh], v);
                al[hh] = __expf(m[hh] - mn);
                m[hh] = mn;
                float rs = 0.f;
#pragma unroll
                for (int nt = 0; nt < 8; nt++) {
                    float p0 = __expf(s[nt][hh * 2]     - mn);
                    float p1 = __expf(s[nt][hh * 2 + 1] - mn);
                    s[nt][hh * 2] = p0; s[nt][hh * 2 + 1] = p1;
                    rs += p0 + p1;
                }
                rs += __shfl_xor_sync(0xffffffffu, rs, 1);
                rs += __shfl_xor_sync(0xffffffffu, rs, 2);
                l[hh] = l[hh] * al[hh] + rs;
#pragma unroll
                for (int cc = 0; cc < 32; cc++) {
                    o[cc][hh * 2]     *= al[hh];
                    o[cc][hh * 2 + 1] *= al[hh];
                }
            }

#pragma unroll
            for (int kk4 = 0; kk4 < 4; kk4++) {
                unsigned pa[4];
                pa[0] = pack_h2(s[2*kk4][0],   s[2*kk4][1]);
                pa[1] = pack_h2(s[2*kk4][2],   s[2*kk4][3]);
                pa[2] = pack_h2(s[2*kk4+1][0], s[2*kk4+1][1]);
                pa[3] = pack_h2(s[2*kk4+1][2], s[2*kk4+1][3]);
#pragma unroll
                for (int half = 0; half < 2; half++) {
                    unsigned bv[8][4];
#pragma unroll
                    for (int p = 0; p < 8; p++)
                        ldsm4(bv[p], Vd + (half * 128 + p * 16 + b_row) * VS_STR + kk4 * 16 + b_kh);
#pragma unroll
                    for (int nt = 0; nt < 16; nt++)
                        mma_f16(o[half * 16 + nt], pa, &bv[nt >> 1][(nt & 1) * 2]);
                }
            }
        }

        __syncthreads();
        if (kt + 2 <= ktmax) issueKV(kt + 2, st);
    }

    // ---- epilogue: /l, * sigmoid(gate) ----
#pragma unroll
    for (int hh = 0; hh < 2; hh++) {
        const int row = q0 + rb + hh * 8 + g;
        const size_t token = (size_t)b * SS + row;
        const float inv = 1.f / l[hh];
#pragma unroll
        for (int cc = 0; cc < 32; cc++) {
            const int col = cc * 8 + 2 * t;
            __half2 gt2 = *(const __half2*)(g_qg + token * QGN + h * 512 + 256 + col);
            float2 gt = __half22float2(gt2);
            float ox = o[cc][hh * 2]     * inv / (1.f + __expf(-gt.x));
            float oy = o[cc][hh * 2 + 1] * inv / (1.f + __expf(-gt.y));
            *(__half2*)(g_attn + token * ODIM + h * 256 + col) =
                __floats2half2_rn(ox, oy);
        }
    }
}

// ---------------------------------------------------------------------------
extern "C" void kernel_launch(void* const* d_in, const int* in_sizes, int n_in,
                              void* d_out, int out_size)
{
    (void)in_sizes; (void)n_in; (void)out_size;
    const float* hs   = (const float*)d_in[0];
    const float* cosp = (const float*)d_in[1];
    const float* sinp = (const float*)d_in[2];
    const float* Wq   = (const float*)d_in[3];
    const float* Wk   = (const float*)d_in[4];
    const float* Wv   = (const float*)d_in[5];
    const float* Wo   = (const float*)d_in[6];
    const float* qw   = (const float*)d_in[7];
    const float* kw   = (const float*)d_in[8];
    float* out = (float*)d_out;

    __half *p_hs, *p_wqt, *p_wkvt, *p_wot, *p_attn, *p_qg, *p_kv;
    cudaGetSymbolAddress((void**)&p_hs,   g_hs);
    cudaGetSymbolAddress((void**)&p_wqt,  g_wqt);
    cudaGetSymbolAddress((void**)&p_wkvt, g_wkvt);
    cudaGetSymbolAddress((void**)&p_wot,  g_wot);
    cudaGetSymbolAddress((void**)&p_qg,   g_qg);
    cudaGetSymbolAddress((void**)&p_kv,   g_kv);
    cudaGetSymbolAddress((void**)&p_attn, g_attn);

    // 0) Prep
    half_kernel<<<1024, 256>>>(hs, p_hs, MM * HID / 8);
    transpose_half_kernel<<<dim3(QGN / 32, HID / 32), dim3(32, 8)>>>(Wq, p_wqt, HID, QGN);
    transpose_half_kernel<<<dim3(KVN / 32, HID / 32), dim3(32, 8)>>>(Wk, p_wkvt, HID, KVN);
    transpose_half_kernel<<<dim3(KVN / 32, HID / 32), dim3(32, 8)>>>(Wv, p_wkvt + (size_t)KVN * HID, HID, KVN);
    transpose_half_kernel<<<dim3(HID / 32, ODIM / 32), dim3(32, 8)>>>(Wo, p_wot, ODIM, HID);

    // 1) Fused QG + KV projection (fp16 outputs, 128x128 tiles, 2 CTAs/SM)
    cudaFuncSetAttribute(hgemm_kernel, cudaFuncAttributeMaxDynamicSharedMemorySize, TG_SMEM);
    hgemm_kernel<<<dim3(QGN / 128 + 2*KVN / 128, MM / 128), 256, TG_SMEM>>>(
        p_hs, p_wqt, p_qg, QGN, p_wkvt, p_kv, 2*KVN, HID, QGN / 128, 1);

    // 2) RMSNorm + RoPE + V transpose
    qkv_post_kernel<<<MM * 20 / 8, 256>>>(cosp, sinp, qw, kw);

    // 3) Flash attention + gate (K+V double-buffered)
    cudaFuncSetAttribute(flash_kernel, cudaFuncAttributeMaxDynamicSharedMemorySize, FL_SMEM);
    flash_kernel<<<dim3(BB * NH, SS / 128), 256, FL_SMEM>>>();

    // 4) Output projection (fp32 output)
    hgemm_kernel<<<dim3(HID / 128, MM / 128), 256, TG_SMEM>>>(
        p_attn, p_wot, out, HID, p_wot, out, HID, ODIM, HID / 128, 0);
}

// round 15
// speedup vs baseline: 1.6351x; 1.0768x over previous
#include <cuda_runtime.h>
#include <cuda_fp16.h>
#include <math.h>

// Problem constants
#define BB 2
#define SS 2048
#define HID 2048
#define NH 16
#define NKVH 2
#define DH 256
#define ROT 64
#define MM (BB*SS)          // 4096 tokens
#define QGN (NH*DH*2)       // 8192
#define KVN (NKVH*DH)       // 512
#define ODIM (NH*DH)        // 4096

// Scratch (device globals)
__device__ __half g_hs  [(size_t)MM * HID];
__device__ __half g_wqt [(size_t)QGN * HID];
__device__ __half g_wkvt[(size_t)(2*KVN) * HID];     // [Wk^T ; Wv^T]
__device__ __half g_wot [(size_t)HID * ODIM];
__device__ __half g_qg  [(size_t)MM * QGN];          // fp16
__device__ __half g_kv  [(size_t)MM * KVN];          // fp16, K only
__device__ __half g_q   [(size_t)BB * NH  * SS * DH];
__device__ __half g_kr  [(size_t)BB * NKVH * SS * DH];
__device__ __half g_vr  [(size_t)KVN * MM];          // [kvh*256+d][b*2048+s]
__device__ __half g_attn[(size_t)MM * ODIM];

// ---------------- device helpers ----------------
__device__ __forceinline__ unsigned smem_u32(const void* p) {
    unsigned a;
    asm("{ .reg .u64 t; cvta.to.shared.u64 t, %1; cvt.u32.u64 %0, t; }" : "=r"(a) : "l"(p));
    return a;
}
__device__ __forceinline__ void mma_f16(float c[4], const unsigned a[4], const unsigned* b) {
    asm volatile(
        "mma.sync.aligned.m16n8k16.row.col.f32.f16.f16.f32 "
        "{%0,%1,%2,%3}, {%4,%5,%6,%7}, {%8,%9}, {%0,%1,%2,%3};\n"
        : "+f"(c[0]), "+f"(c[1]), "+f"(c[2]), "+f"(c[3])
        : "r"(a[0]), "r"(a[1]), "r"(a[2]), "r"(a[3]), "r"(b[0]), "r"(b[1]));
}
__device__ __forceinline__ void ldsm4(unsigned r[4], const __half* p) {
    unsigned a = smem_u32(p);
    asm volatile("ldmatrix.sync.aligned.m8n8.x4.shared.b16 {%0,%1,%2,%3}, [%4];\n"
                 : "=r"(r[0]), "=r"(r[1]), "=r"(r[2]), "=r"(r[3]) : "r"(a));
}
__device__ __forceinline__ void cp16(void* dst, const void* src) {
    unsigned d = (unsigned)__cvta_generic_to_shared(dst);
    asm volatile("cp.async.cg.shared.global [%0], [%1], 16;\n" :: "r"(d), "l"(src));
}
__device__ __forceinline__ void cp_commit() { asm volatile("cp.async.commit_group;\n"); }
__device__ __forceinline__ unsigned pack_h2(float a, float b) {
    __half2 h = __floats2half2_rn(a, b);
    return *(unsigned*)&h;
}

// ---------------------------------------------------------------------------
// Merged prep kernel: 1D grid with sections.
//   [0, 1024)        : hs fp32 -> fp16 (grid-stride)
//   [1024, +16384)   : Wq transpose  (R=HID, C=QGN)
//   [+, +1024)       : Wk transpose  (R=HID, C=KVN) -> wkvt
//   [+, +1024)       : Wv transpose  (R=HID, C=KVN) -> wkvt + KVN*HID
//   [+, +8192)       : Wo transpose  (R=ODIM, C=HID)
// ---------------------------------------------------------------------------
#define NB_HS 1024
#define NB_WQ ((QGN/32)*(HID/32))   // 16384
#define NB_WK ((KVN/32)*(HID/32))   // 1024
#define NB_WO ((HID/32)*(ODIM/32))  // 8192
#define NB_PREP (NB_HS + NB_WQ + 2*NB_WK + NB_WO)

__device__ __forceinline__ void tr_tile(
    float (*t)[33], const float* __restrict__ src, __half* __restrict__ dst,
    int R, int C, int bx, int by, int tid)
{
    const int tx = tid & 31, ty = tid >> 5;
    const int x = bx * 32 + tx;
    const int y0 = by * 32;
#pragma unroll
    for (int i = 0; i < 4; i++)
        t[ty + i * 8][tx] = src[(size_t)(y0 + ty + i * 8) * C + x];
    __syncthreads();
    const int nx = by * 32 + tx;
    const int ny0 = bx * 32;
#pragma unroll
    for (int i = 0; i < 4; i++)
        dst[(size_t)(ny0 + ty + i * 8) * R + nx] = __float2half(t[tx][ty + i * 8]);
}

__global__ __launch_bounds__(256) void prep_kernel(
    const float* __restrict__ hs,
    const float* __restrict__ Wq, const float* __restrict__ Wk,
    const float* __restrict__ Wv, const float* __restrict__ Wo)
{
    __shared__ float t[32][33];
    const int tid = threadIdx.x;
    int id = blockIdx.x;

    if (id < NB_HS) {
        const int n8 = MM * HID / 8;
        for (int i = id * 256 + tid; i < n8; i += NB_HS * 256) {
            float4 v0 = ((const float4*)hs)[i * 2];
            float4 v1 = ((const float4*)hs)[i * 2 + 1];
            __half2 h[4];
            h[0] = __floats2half2_rn(v0.x, v0.y);
            h[1] = __floats2half2_rn(v0.z, v0.w);
            h[2] = __floats2half2_rn(v1.x, v1.y);
            h[3] = __floats2half2_rn(v1.z, v1.w);
            ((uint4*)g_hs)[i] = *(uint4*)h;
        }
        return;
    }
    id -= NB_HS;
    if (id < NB_WQ) {
        tr_tile(t, Wq, g_wqt, HID, QGN, id % (QGN/32), id / (QGN/32), tid);
        return;
    }
    id -= NB_WQ;
    if (id < NB_WK) {
        tr_tile(t, Wk, g_wkvt, HID, KVN, id % (KVN/32), id / (KVN/32), tid);
        return;
    }
    id -= NB_WK;
    if (id < NB_WK) {
        tr_tile(t, Wv, g_wkvt + (size_t)KVN * HID, HID, KVN, id % (KVN/32), id / (KVN/32), tid);
        return;
    }
    id -= NB_WK;
    tr_tile(t, Wo, g_wot, ODIM, HID, id % (HID/32), id / (HID/32), tid);
}

// ---------------------------------------------------------------------------
// fp16 GEMM shared mainloop config: CTA tile 128x128, BK=32, 3-stage,
// 8 warps (4 wm x 2 wn), warp 32x64, 2 CTAs/SM.
// ---------------------------------------------------------------------------
#define GS_STR 40
#define TG_SMEM ((3*128*GS_STR + 3*128*GS_STR) * (int)sizeof(__half))

// QKV projection: 1D grid, 3 segments, all K=HID, fp16 out.
//  [0,2048):    QG  = hs @ WqT   (N=QGN)
//  [2048,2176): K   = hs @ WkT   (N=KVN)
//  [2176,2304): V^T = WvT @ hsT  (N=MM)   -> g_vr [n][token]
__global__ __launch_bounds__(256, 2) void hgemm_qkv_kernel()
{
    extern __shared__ __half hsm[];
    __half* As = hsm;                        // [3][128][GS_STR]
    __half* Bs = hsm + 3 * 128 * GS_STR;     // [3][128][GS_STR]

    const int tid = threadIdx.x;
    int cid = blockIdx.x;
    const __half *A, *Bt; __half* C; int N, bx, by;
    if (cid < 2048)      { A = g_hs; Bt = g_wqt; C = g_qg; N = QGN; bx = cid & 63; by = cid >> 6; }
    else if (cid < 2176) { cid -= 2048; A = g_hs; Bt = g_wkvt; C = g_kv; N = KVN; bx = cid & 3; by = cid >> 2; }
    else                 { cid -= 2176; A = g_wkvt + (size_t)KVN * HID; Bt = g_hs; C = g_vr; N = MM; bx = cid & 31; by = cid >> 5; }

    const int lane = tid & 31;
    const int g = lane >> 2, t = lane & 3;
    const int wid = tid >> 5;
    const int m0 = (wid >> 1) * 32;
    const int n0 = (wid & 1) * 64;

    const int a_row = ((lane >> 3) & 1) * 8 + (lane & 7);
    const int a_kh  = (lane >> 4) * 8;
    const int b_row = ((lane >> 4) & 1) * 8 + (lane & 7);
    const int b_kh  = ((lane >> 3) & 1) * 8;

    const int nk = HID >> 5;

    auto issue = [&](int st, int k0) {
        __half* Ad = As + (size_t)st * 128 * GS_STR;
        __half* Bd = Bs + (size_t)st * 128 * GS_STR;
#pragma unroll
        for (int it = 0; it < 2; it++) {
            int idx = tid + it * 256;
            int row = idx >> 2;
            int ch  = (idx & 3) * 8;
            cp16(Ad + row * GS_STR + ch, A + (size_t)(by * 128 + row) * HID + k0 + ch);
            cp16(Bd + row * GS_STR + ch, Bt + (size_t)(bx * 128 + row) * HID + k0 + ch);
        }
        cp_commit();
    };

    issue(0, 0);
    issue(1, 32);
    issue(2, 64);

    float acc[2][8][4];
#pragma unroll
    for (int mt = 0; mt < 2; mt++)
#pragma unroll
        for (int nt = 0; nt < 8; nt++)
#pragma unroll
            for (int r = 0; r < 4; r++) acc[mt][nt][r] = 0.f;

    for (int i = 0; i < nk; i++) {
        const int st = i % 3;
        __half* Ad = As + (size_t)st * 128 * GS_STR;
        __half* Bd = Bs + (size_t)st * 128 * GS_STR;
        if (i + 2 < nk)      asm volatile("cp.async.wait_group 2;\n");
        else if (i + 1 < nk) asm volatile("cp.async.wait_group 1;\n");
        else                 asm volatile("cp.async.wait_group 0;\n");
        __syncthreads();

#pragma unroll
        for (int kk = 0; kk < 32; kk += 16) {
            unsigned a[2][4], bfr[4][4];
#pragma unroll
            for (int mt = 0; mt < 2; mt++)
                ldsm4(a[mt], Ad + (m0 + mt * 16 + a_row) * GS_STR + kk + a_kh);
#pragma unroll
            for (int p = 0; p < 4; p++)
                ldsm4(bfr[p], Bd + (n0 + p * 16 + b_row) * GS_STR + kk + b_kh);
#pragma unroll
            for (int mt = 0; mt < 2; mt++)
#pragma unroll
                for (int nt = 0; nt < 8; nt++)
                    mma_f16(acc[mt][nt], a[mt], &bfr[nt >> 1][(nt & 1) * 2]);
        }
        __syncthreads();
        if (i + 3 < nk) issue(st, (i + 3) * 32);
    }

#pragma unroll
    for (int mt = 0; mt < 2; mt++) {
        const int r = by * 128 + m0 + mt * 16 + g;
#pragma unroll
        for (int nt = 0; nt < 8; nt++) {
            const int c = bx * 128 + n0 + nt * 8 + 2 * t;
            *(__half2*)(C + (size_t)r * N + c) =
                __floats2half2_rn(acc[mt][nt][0], acc[mt][nt][1]);
            *(__half2*)(C + (size_t)(r + 8) * N + c) =
                __floats2half2_rn(acc[mt][nt][2], acc[mt][nt][3]);
        }
    }
}

// O-projection: out = attn @ WoT, fp32 out. Grid (32, 32).
__global__ __launch_bounds__(256, 2) void hgemm_o_kernel(float* __restrict__ out)
{
    extern __shared__ __half hsm[];
    __half* As = hsm;
    __half* Bs = hsm + 3 * 128 * GS_STR;

    const int tid = threadIdx.x;
    const int bx = blockIdx.x, by = blockIdx.y;
    const __half* A  = g_attn;
    const __half* Bt = g_wot;
    const int N = HID;

    const int lane = tid & 31;
    const int g = lane >> 2, t = lane & 3;
    const int wid = tid >> 5;
    const int m0 = (wid >> 1) * 32;
    const int n0 = (wid & 1) * 64;

    const int a_row = ((lane >> 3) & 1) * 8 + (lane & 7);
    const int a_kh  = (lane >> 4) * 8;
    const int b_row = ((lane >> 4) & 1) * 8 + (lane & 7);
    const int b_kh  = ((lane >> 3) & 1) * 8;

    const int nk = ODIM >> 5;

    auto issue = [&](int st, int k0) {
        __half* Ad = As + (size_t)st * 128 * GS_STR;
        __half* Bd = Bs + (size_t)st * 128 * GS_STR;
#pragma unroll
        for (int it = 0; it < 2; it++) {
            int idx = tid + it * 256;
            int row = idx >> 2;
            int ch  = (idx & 3) * 8;
            cp16(Ad + row * GS_STR + ch, A + (size_t)(by * 128 + row) * ODIM + k0 + ch);
            cp16(Bd + row * GS_STR + ch, Bt + (size_t)(bx * 128 + row) * ODIM + k0 + ch);
        }
        cp_commit();
    };

    issue(0, 0);
    issue(1, 32);
    issue(2, 64);

    float acc[2][8][4];
#pragma unroll
    for (int mt = 0; mt < 2; mt++)
#pragma unroll
        for (int nt = 0; nt < 8; nt++)
#pragma unroll
            for (int r = 0; r < 4; r++) acc[mt][nt][r] = 0.f;

    for (int i = 0; i < nk; i++) {
        const int st = i % 3;
        __half* Ad = As + (size_t)st * 128 * GS_STR;
        __half* Bd = Bs + (size_t)st * 128 * GS_STR;
        if (i + 2 < nk)      asm volatile("cp.async.wait_group 2;\n");
        else if (i + 1 < nk) asm volatile("cp.async.wait_group 1;\n");
        else                 asm volatile("cp.async.wait_group 0;\n");
        __syncthreads();

#pragma unroll
        for (int kk = 0; kk < 32; kk += 16) {
            unsigned a[2][4], bfr[4][4];
#pragma unroll
            for (int mt = 0; mt < 2; mt++)
                ldsm4(a[mt], Ad + (m0 + mt * 16 + a_row) * GS_STR + kk + a_kh);
#pragma unroll
            for (int p = 0; p < 4; p++)
                ldsm4(bfr[p], Bd + (n0 + p * 16 + b_row) * GS_STR + kk + b_kh);
#pragma unroll
            for (int mt = 0; mt < 2; mt++)
#pragma unroll
                for (int nt = 0; nt < 8; nt++)
                    mma_f16(acc[mt][nt], a[mt], &bfr[nt >> 1][(nt & 1) * 2]);
        }
        __syncthreads();
        if (i + 3 < nk) issue(st, (i + 3) * 32);
    }

#pragma unroll
    for (int mt = 0; mt < 2; mt++) {
        const int r = by * 128 + m0 + mt * 16 + g;
#pragma unroll
        for (int nt = 0; nt < 8; nt++) {
            const int c = bx * 128 + n0 + nt * 8 + 2 * t;
            *(float2*)(out + (size_t)r * N + c)       = make_float2(acc[mt][nt][0], acc[mt][nt][1]);
            *(float2*)(out + (size_t)(r + 8) * N + c) = make_float2(acc[mt][nt][2], acc[mt][nt][3]);
        }
    }
}

// ---------------------------------------------------------------------------
// Post-process: one WARP per (token, unit); 18 units (16 Q + 2 K).
// ---------------------------------------------------------------------------
__global__ __launch_bounds__(256) void qkv_post_kernel(
    const float* __restrict__ cosp, const float* __restrict__ sinp,
    const float* __restrict__ qw, const float* __restrict__ kw)
{
    const int wi = blockIdx.x * 8 + (threadIdx.x >> 5);
    const int lane = threadIdx.x & 31;
    const int token = wi / 18;
    const int unit  = wi % 18;
    const int b = token >> 11;
    const int s = token & 2047;
    const int d0 = lane * 8;

    const __half* src;
    const float* w;
    if (unit < 16) { src = g_qg + (size_t)token * QGN + unit * 512 + d0; w = qw + d0; }
    else           { src = g_kv + (size_t)token * KVN + (unit - 16) * 256 + d0; w = kw + d0; }

    uint4 raw = *(const uint4*)src;
    const __half* hx = (const __half*)&raw;
    float x[8];
#pragma unroll
    for (int j = 0; j < 8; j++) x[j] = __half2float(hx[j]);

    float ss = 0.f;
#pragma unroll
    for (int j = 0; j < 8; j++) ss += x[j] * x[j];
#pragma unroll
    for (int o = 16; o; o >>= 1) ss += __shfl_xor_sync(0xffffffffu, ss, o);
    const float rsn = rsqrtf(ss * (1.0f / 256.0f) + 1e-6f);

    float xn[8];
#pragma unroll
    for (int j = 0; j < 8; j++) xn[j] = x[j] * rsn * (1.0f + w[j]);

    float rot[8];
#pragma unroll
    for (int j = 0; j < 8; j++) rot[j] = __shfl_xor_sync(0xffffffffu, xn[j], 4);
    if (lane < 8) {
        float cs[8], sn[8];
        *(float4*)(cs)     = *(const float4*)(cosp + (size_t)token * ROT + d0);
        *(float4*)(cs + 4) = *(const float4*)(cosp + (size_t)token * ROT + d0 + 4);
        *(float4*)(sn)     = *(const float4*)(sinp + (size_t)token * ROT + d0);
        *(float4*)(sn + 4) = *(const float4*)(sinp + (size_t)token * ROT + d0 + 4);
#pragma unroll
        for (int j = 0; j < 8; j++) {
            float rr = (lane & 4) ? rot[j] : -rot[j];
            xn[j] = xn[j] * cs[j] + rr * sn[j];
        }
    }

    __half2 h[4];
    if (unit < 16) {
#pragma unroll
        for (int j = 0; j < 4; j++)
            h[j] = __floats2half2_rn(xn[2*j] * 0.0625f, xn[2*j+1] * 0.0625f);
        *(uint4*)(g_q + (((size_t)b * NH + unit) * SS + s) * DH + d0) = *(uint4*)h;
    } else {
#pragma unroll
        for (int j = 0; j < 4; j++)
            h[j] = __floats2half2_rn(xn[2*j], xn[2*j+1]);
        *(uint4*)(g_kr + (((size_t)b * NKVH + (unit - 16)) * SS + s) * DH + d0) = *(uint4*)h;
    }
}

// ---------------------------------------------------------------------------
// Flash attention v8: warp-autonomous, register-resident P, K+V double-
// buffered, heavy q-tiles first, masked-warp skip. g_vr is [n][b*SS+s].
// ---------------------------------------------------------------------------
#define QS_STR 264
#define KS_STR 264
#define VS_STR 72
#define FL_SMEM ((128*QS_STR + 2*64*KS_STR + 2*256*VS_STR) * 2)

__global__ __launch_bounds__(256, 1) void flash_kernel()
{
    extern __shared__ __half smh[];
    __half* Qs = smh;                        // [128][QS_STR]
    __half* Ks = Qs + 128 * QS_STR;          // [2][64][KS_STR]
    __half* Vs = Ks + 2 * 64 * KS_STR;       // [2][256][VS_STR] ([d][key])

    const int tid = threadIdx.x;
    const int lane = tid & 31;
    const int g = lane >> 2, t = lane & 3;
    const int w = tid >> 5;
    const int rb = w * 16;

    const int a_row = ((lane >> 3) & 1) * 8 + (lane & 7);
    const int a_kh  = (lane >> 4) * 8;
    const int b_row = ((lane >> 4) & 1) * 8 + (lane & 7);
    const int b_kh  = ((lane >> 3) & 1) * 8;

    const int qt = (int)gridDim.y - 1 - (int)blockIdx.y;   // heavy first
    const int b  = blockIdx.x >> 4;
    const int h  = blockIdx.x & 15;
    const int kvh = h >> 3;
    const int q0 = qt * 128;

    const __half* Qp  = g_q  + (((size_t)b * NH + h) * SS + q0) * DH;
    const __half* Kp  = g_kr + ((size_t)b * NKVH + kvh) * SS * DH;
    const __half* VpT = g_vr + (size_t)(kvh * DH) * MM + (size_t)b * SS;

    auto issueKV = [&](int kt, int st) {
        const __half* Kt = Kp + (size_t)(kt * 64) * DH;
        __half* Kd = Ks + st * 64 * KS_STR;
        __half* Vd = Vs + st * 256 * VS_STR;
#pragma unroll
        for (int it = 0; it < 8; it++) {
            const int idx = tid + it * 256;
            const int key = idx >> 5;
            const int col = (idx & 31) * 8;
            cp16(Kd + key * KS_STR + col, Kt + (size_t)key * DH + col);
            const int dl = idx >> 3;
            const int kc = (idx & 7) * 8;
            cp16(Vd + dl * VS_STR + kc, VpT + (size_t)dl * MM + kt * 64 + kc);
        }
        cp_commit();
    };

    // Q resident
#pragma unroll
    for (int it = 0; it < 16; it++) {
        const int idx = tid + it * 256;
        const int r = idx >> 5;
        const int c = (idx & 31) * 8;
        *(uint4*)&Qs[r * QS_STR + c] = *(const uint4*)(Qp + (size_t)r * DH + c);
    }

    float o[32][4];
    float m[2], l[2];
#pragma unroll
    for (int cc = 0; cc < 32; cc++)
#pragma unroll
        for (int r = 0; r < 4; r++) o[cc][r] = 0.f;
    m[0] = m[1] = -1e30f; l[0] = l[1] = 0.f;

    const int ktmax = 2 * qt + 1;

    issueKV(0, 0);
    issueKV(1, 1);

    for (int kt = 0; kt <= ktmax; kt++) {
        const int st = kt & 1;
        if (kt + 1 <= ktmax) asm volatile("cp.async.wait_group 1;\n");
        else                 asm volatile("cp.async.wait_group 0;\n");
        __syncthreads();

        const bool active = (kt * 64 <= q0 + rb + 15);

        float s[8][4];
        if (active) {
            const __half* Kd = Ks + st * 64 * KS_STR;
            const __half* Vd = Vs + st * 256 * VS_STR;
#pragma unroll
            for (int nt = 0; nt < 8; nt++)
#pragma unroll
                for (int r = 0; r < 4; r++) s[nt][r] = 0.f;

#pragma unroll
            for (int kk = 0; kk < 256; kk += 16) {
                unsigned a[4], bq[4][4];
                ldsm4(a, Qs + (rb + a_row) * QS_STR + kk + a_kh);
#pragma unroll
                for (int p = 0; p < 4; p++)
                    ldsm4(bq[p], Kd + (p * 16 + b_row) * KS_STR + kk + b_kh);
#pragma unroll
                for (int nt = 0; nt < 8; nt++)
                    mma_f16(s[nt], a, &bq[nt >> 1][(nt & 1) * 2]);
            }

            if (kt >= 2 * qt) {
#pragma unroll
                for (int nt = 0; nt < 8; nt++)
#pragma unroll
                    for (int r = 0; r < 4; r++) {
                        const int row = q0 + rb + (r >> 1) * 8 + g;
                        const int col = kt * 64 + nt * 8 + 2 * t + (r & 1);
                        if (col > row) s[nt][r] = -1e30f;
                    }
            }

            float al[2];
#pragma unroll
            for (int hh = 0; hh < 2; hh++) {
                float v = -1e30f;
#pragma unroll
                for (int nt = 0; nt < 8; nt++)
                    v = fmaxf(v, fmaxf(s[nt][hh * 2], s[nt][hh * 2 + 1]));
                v = fmaxf(v, __shfl_xor_sync(0xffffffffu, v, 1));
                v = fmaxf(v, __shfl_xor_sync(0xffffffffu, v, 2));
                float mn = fmaxf(m[hh], v);
                al[hh] = __expf(m[hh] - mn);
                m[hh] = mn;
                float rs = 0.f;
#pragma unroll
                for (int nt = 0; nt < 8; nt++) {
                    float p0 = __expf(s[nt][hh * 2]     - mn);
                    float p1 = __expf(s[nt][hh * 2 + 1] - mn);
                    s[nt][hh * 2] = p0; s[nt][hh * 2 + 1] = p1;
                    rs += p0 + p1;
                }
                rs += __shfl_xor_sync(0xffffffffu, rs, 1);
                rs += __shfl_xor_sync(0xffffffffu, rs, 2);
                l[hh] = l[hh] * al[hh] + rs;
#pragma unroll
                for (int cc = 0; cc < 32; cc++) {
                    o[cc][hh * 2]     *= al[hh];
                    o[cc][hh * 2 + 1] *= al[hh];
                }
            }

#pragma unroll
            for (int kk4 = 0; kk4 < 4; kk4++) {
                unsigned pa[4];
                pa[0] = pack_h2(s[2*kk4][0],   s[2*kk4][1]);
                pa[1] = pack_h2(s[2*kk4][2],   s[2*kk4][3]);
                pa[2] = pack_h2(s[2*kk4+1][0], s[2*kk4+1][1]);
                pa[3] = pack_h2(s[2*kk4+1][2], s[2*kk4+1][3]);
#pragma unroll
                for (int half = 0; half < 2; half++) {
                    unsigned bv[8][4];
#pragma unroll
                    for (int p = 0; p < 8; p++)
                        ldsm4(bv[p], Vd + (half * 128 + p * 16 + b_row) * VS_STR + kk4 * 16 + b_kh);
#pragma unroll
                    for (int nt = 0; nt < 16; nt++)
                        mma_f16(o[half * 16 + nt], pa, &bv[nt >> 1][(nt & 1) * 2]);
                }
            }
        }

        __syncthreads();
        if (kt + 2 <= ktmax) issueKV(kt + 2, st);
    }

    // ---- epilogue: /l, * sigmoid(gate) ----
#pragma unroll
    for (int hh = 0; hh < 2; hh++) {
        const int row = q0 + rb + hh * 8 + g;
        const size_t token = (size_t)b * SS + row;
        const float inv = 1.f / l[hh];
#pragma unroll
        for (int cc = 0; cc < 32; cc++) {
            const int col = cc * 8 + 2 * t;
            __half2 gt2 = *(const __half2*)(g_qg + token * QGN + h * 512 + 256 + col);
            float2 gt = __half22float2(gt2);
            float ox = o[cc][hh * 2]     * inv / (1.f + __expf(-gt.x));
            float oy = o[cc][hh * 2 + 1] * inv / (1.f + __expf(-gt.y));
            *(__half2*)(g_attn + token * ODIM + h * 256 + col) =
                __floats2half2_rn(ox, oy);
        }
    }
}

// ---------------------------------------------------------------------------
extern "C" void kernel_launch(void* const* d_in, const int* in_sizes, int n_in,
                              void* d_out, int out_size)
{
    (void)in_sizes; (void)n_in; (void)out_size;
    const float* hs   = (const float*)d_in[0];
    const float* cosp = (const float*)d_in[1];
    const float* sinp = (const float*)d_in[2];
    const float* Wq   = (const float*)d_in[3];
    const float* Wk   = (const float*)d_in[4];
    const float* Wv   = (const float*)d_in[5];
    const float* Wo   = (const float*)d_in[6];
    const float* qw   = (const float*)d_in[7];
    const float* kw   = (const float*)d_in[8];
    float* out = (float*)d_out;

    // 0) Prep (single launch)
    prep_kernel<<<NB_PREP, 256>>>(hs, Wq, Wk, Wv, Wo);

    // 1) QG + K + V^T projections (one 1D launch, 2304 CTAs, 2/SM)
    cudaFuncSetAttribute(hgemm_qkv_kernel, cudaFuncAttributeMaxDynamicSharedMemorySize, TG_SMEM);
    hgemm_qkv_kernel<<<2304, 256, TG_SMEM>>>();

    // 2) RMSNorm + RoPE (Q, K only)
    qkv_post_kernel<<<MM * 18 / 8, 256>>>(cosp, sinp, qw, kw);

    // 3) Flash attention + gate
    cudaFuncSetAttribute(flash_kernel, cudaFuncAttributeMaxDynamicSharedMemorySize, FL_SMEM);
    flash_kernel<<<dim3(BB * NH, SS / 128), 256, FL_SMEM>>>();

    // 4) Output projection (fp32 out)
    cudaFuncSetAttribute(hgemm_o_kernel, cudaFuncAttributeMaxDynamicSharedMemorySize, TG_SMEM);
    hgemm_o_kernel<<<dim3(HID / 128, MM / 128), 256, TG_SMEM>>>(out);
}